// round 9
// baseline (speedup 1.0000x reference)
#include <cuda_runtime.h>
#include <cuda_bf16.h>
#include <math.h>
#include <cstdint>

// Problem constants
#define BATCH   128
#define NNODE   64
#define TDIM    256
#define KIN     320          // N + T
#define HDIM    256
#define ODIM    128
#define EPG     2016         // edges per graph
#define TEDGE   (BATCH*EPG)  // 258048
#define MROWS   (BATCH*NNODE)// 8192
#define PW      512          // packed mean/var head width
#define PSTR    532          // smem row stride (x4B: 2128B; mod 128B = 80 -> conflict-free LDS.128)

// mma staging: k-chunk 64, row stride 36 b32 (conflict-free frag loads)
#define KC      64
#define BSTR    36           // b32 per staged row
#define REG_U32 (128 * BSTR) // 4608 u32 per tile region
#define MM_SMEM (4 * REG_U32 * 4)  // 73728 bytes
#define ED_SMEM (NNODE * PSTR * 4) // 136192 bytes

// ---------------- device scratch (static, allocation-free) ----------------
__device__ float g_h     [MROWS * HDIM];   //  8.4 MB
__device__ float g_WgnnT [HDIM * KIN];     //  0.33 MB  (Wgnn^T: [256][320])
__device__ float g_WcatT [PW * HDIM];      //  0.52 MB  (packed heads^T: [512][256])
__device__ float g_P     [MROWS * PW];     // 16.8 MB
__device__ float g_Pw    [MROWS * 2];      //  64 KB
__device__ float g_simnum[TEDGE];          //  1.0 MB
__device__ float g_partials[BATCH];

// ==================== mma.sync helpers (baseline PTX, sm_80+) ==============
__device__ __forceinline__ void mma_bf16(float* c, const uint32_t* a, const uint32_t* b) {
    asm volatile(
        "mma.sync.aligned.m16n8k16.row.col.f32.bf16.bf16.f32 "
        "{%0,%1,%2,%3}, {%4,%5,%6,%7}, {%8,%9}, {%0,%1,%2,%3};"
        : "+f"(c[0]), "+f"(c[1]), "+f"(c[2]), "+f"(c[3])
        : "r"(a[0]), "r"(a[1]), "r"(a[2]), "r"(a[3]), "r"(b[0]), "r"(b[1]));
}

// split two floats into packed bf16x2 hi and lo (low 16 bits = first element)
__device__ __forceinline__ void cvt2(float a, float b, uint32_t& hi, uint32_t& lo) {
    __nv_bfloat16 ha = __float2bfloat16_rn(a), hb = __float2bfloat16_rn(b);
    float ra = a - __bfloat162float(ha), rb = b - __bfloat162float(hb);
    __nv_bfloat16 la = __float2bfloat16_rn(ra), lb = __float2bfloat16_rn(rb);
    hi = ((uint32_t)__bfloat16_as_ushort(hb) << 16) | (uint32_t)__bfloat16_as_ushort(ha);
    lo = ((uint32_t)__bfloat16_as_ushort(lb) << 16) | (uint32_t)__bfloat16_as_ushort(la);
}

// load 128x64 f32 tile into registers (8 float4 / thread)
__device__ __forceinline__ void ld_tile(const float* __restrict__ g, int gstride,
                                        int tid, float4* buf) {
    const float* src = g + (tid >> 1) * gstride + (tid & 1) * 32;
#pragma unroll
    for (int q = 0; q < 8; ++q) buf[q] = *(const float4*)(src + q * 4);
}

// convert + store registers into hi/lo bf16x2 staging tiles
__device__ __forceinline__ void st_tile(uint32_t* __restrict__ sh, uint32_t* __restrict__ sl,
                                        int tid, const float4* buf) {
    uint32_t* dh = sh + (tid >> 1) * BSTR + (tid & 1) * 16;
    uint32_t* dl = sl + (tid >> 1) * BSTR + (tid & 1) * 16;
#pragma unroll
    for (int q = 0; q < 8; ++q) {
        uint32_t h0, l0, h1, l1;
        cvt2(buf[q].x, buf[q].y, h0, l0);
        cvt2(buf[q].z, buf[q].w, h1, l1);
        dh[2 * q] = h0; dh[2 * q + 1] = h1;
        dl[2 * q] = l0; dl[2 * q + 1] = l1;
    }
}

// one k=64 chunk of bf16x2-compensated mma into acc[2][8][4]
__device__ __forceinline__ void chunk_mma(const uint32_t* __restrict__ sAh,
                                          const uint32_t* __restrict__ sAl,
                                          const uint32_t* __restrict__ sBh,
                                          const uint32_t* __restrict__ sBl,
                                          int wm, int wn, int lane,
                                          float acc[2][8][4]) {
    const int g = lane >> 2, t = lane & 3;
#pragma unroll
    for (int kb = 0; kb < 4; ++kb) {
        const int kc = kb * 8 + t;
        uint32_t Ah[2][4], Al[2][4], Bh[8][2], Bl[8][2];
#pragma unroll
        for (int i = 0; i < 2; ++i) {
            int r = (wm * 32 + 16 * i + g) * BSTR + kc;
            Ah[i][0] = sAh[r];              Ah[i][1] = sAh[r + 8 * BSTR];
            Ah[i][2] = sAh[r + 4];          Ah[i][3] = sAh[r + 8 * BSTR + 4];
            Al[i][0] = sAl[r];              Al[i][1] = sAl[r + 8 * BSTR];
            Al[i][2] = sAl[r + 4];          Al[i][3] = sAl[r + 8 * BSTR + 4];
        }
#pragma unroll
        for (int j = 0; j < 8; ++j) {
            int r = (wn * 64 + 8 * j + g) * BSTR + kc;
            Bh[j][0] = sBh[r]; Bh[j][1] = sBh[r + 4];
            Bl[j][0] = sBl[r]; Bl[j][1] = sBl[r + 4];
        }
#pragma unroll
        for (int i = 0; i < 2; ++i)
#pragma unroll
            for (int j = 0; j < 8; ++j) {
                mma_bf16(acc[i][j], Ah[i], Bh[j]);   // hi*hi
                mma_bf16(acc[i][j], Ah[i], Bl[j]);   // hi*lo
                mma_bf16(acc[i][j], Al[i], Bh[j]);   // lo*hi
            }
    }
}

// ---------------- prep: transpose Wgnn + pack/transpose heads --------------
__global__ void k_prep_T(const float* __restrict__ Wgnn, const float* __restrict__ Wm,
                         const float* __restrict__ Wv) {
    int idx = blockIdx.x * blockDim.x + threadIdx.x;
    if (idx < HDIM * KIN) {
        int n = idx / KIN, k = idx - n * KIN;
        g_WgnnT[idx] = Wgnn[k * HDIM + n];
        return;
    }
    idx -= HDIM * KIN;
    if (idx >= PW * HDIM) return;
    int n = idx >> 8, k = idx & 255;
    float v;
    if      (n < 128) v = Wm[k * ODIM + n];
    else if (n < 256) v = Wm[(HDIM + k) * ODIM + (n - 128)];
    else if (n < 384) v = Wv[k * ODIM + (n - 256)];
    else              v = Wv[(HDIM + k) * ODIM + (n - 384)];
    g_WcatT[idx] = v;
}

// ====== GEMM1 (mma.sync bf16x2, pipelined): h = relu(prefixmean(..)+b) =====
// grid (2, 64), 256 threads. K=320 in 5 chunks of 64. Fused scan epilogue.
__global__ __launch_bounds__(256)
void gemm1_mma(const float* __restrict__ topo, const float* __restrict__ temp,
               const float* __restrict__ bias) {
    extern __shared__ uint32_t sm[];
    uint32_t *sAh = sm, *sAl = sm + REG_U32, *sBh = sm + 2 * REG_U32, *sBl = sm + 3 * REG_U32;
    const int tid = threadIdx.x, lane = tid & 31, wid = tid >> 5;
    const int wm = wid >> 1, wn = wid & 1;
    const int bx = blockIdx.x, by = blockIdx.y;
    const int m0 = by * 128, n0 = bx * 128;

    float acc[2][8][4];
#pragma unroll
    for (int i = 0; i < 2; ++i)
#pragma unroll
        for (int j = 0; j < 8; ++j)
#pragma unroll
            for (int q = 0; q < 4; ++q) acc[i][j][q] = 0.f;

    float4 bufA[8], bufB[8];
    ld_tile(topo + m0 * NNODE, NNODE, tid, bufA);          // chunk 0 A = topo (full row)
    ld_tile(g_WgnnT + n0 * KIN, KIN, tid, bufB);

#pragma unroll 1
    for (int c = 0; c < 5; ++c) {
        __syncthreads();                                    // prior mma done with smem
        st_tile(sAh, sAl, tid, bufA);
        st_tile(sBh, sBl, tid, bufB);
        if (c < 4) {                                        // prefetch chunk c+1
            ld_tile(temp + m0 * TDIM + c * KC, TDIM, tid, bufA);
            ld_tile(g_WgnnT + n0 * KIN + (c + 1) * KC, KIN, tid, bufB);
        }
        __syncthreads();
        chunk_mma(sAh, sAl, sBh, sBl, wm, wn, lane, acc);   // overlaps prefetch latency
    }

    // epilogue: fragments -> smem scan buffer (aliased over staging tiles)
    __syncthreads();
    float* sD = (float*)sm;                 // 128 x 129 floats (66 KB <= 72 KB)
    const int g = lane >> 2, t = lane & 3;
#pragma unroll
    for (int i = 0; i < 2; ++i) {
        int r0 = wm * 32 + 16 * i + g;
#pragma unroll
        for (int j = 0; j < 8; ++j) {
            int cc = wn * 64 + 8 * j + t * 2;
            sD[r0 * 129 + cc]       = acc[i][j][0];
            sD[r0 * 129 + cc + 1]   = acc[i][j][1];
            sD[(r0 + 8) * 129 + cc]     = acc[i][j][2];
            sD[(r0 + 8) * 129 + cc + 1] = acc[i][j][3];
        }
    }
    __syncthreads();

    // prefix-mean + ReLU: 256 threads = 128 cols x 2 graphs
    {
        const int col = tid & 127, gph = tid >> 7;
        const float bv = bias[n0 + col];
        float s = 0.f;
        float* hout = g_h + ((by * 2 + gph) * NNODE) * HDIM + n0 + col;
#pragma unroll 4
        for (int j = 0; j < NNODE; ++j) {
            float agg = (j > 0) ? (s / (float)j) : 0.f;
            hout[j * HDIM] = fmaxf(agg + bv, 0.f);
            s += sD[(gph * NNODE + j) * 129 + col];
        }
    }
}

// ====== GEMM2 (mma.sync bf16x2, pipelined): P = h @ WcatT^T ================
// grid (4, 64), 256 threads. K=256 in 4 chunks of 64.
__global__ __launch_bounds__(256)
void gemm2_mma() {
    extern __shared__ uint32_t sm[];
    uint32_t *sAh = sm, *sAl = sm + REG_U32, *sBh = sm + 2 * REG_U32, *sBl = sm + 3 * REG_U32;
    const int tid = threadIdx.x, lane = tid & 31, wid = tid >> 5;
    const int wm = wid >> 1, wn = wid & 1;
    const int bx = blockIdx.x, by = blockIdx.y;
    const int m0 = by * 128, n0 = bx * 128;

    float acc[2][8][4];
#pragma unroll
    for (int i = 0; i < 2; ++i)
#pragma unroll
        for (int j = 0; j < 8; ++j)
#pragma unroll
            for (int q = 0; q < 4; ++q) acc[i][j][q] = 0.f;

    float4 bufA[8], bufB[8];
    ld_tile(g_h + m0 * HDIM, HDIM, tid, bufA);
    ld_tile(g_WcatT + n0 * HDIM, HDIM, tid, bufB);

#pragma unroll 1
    for (int c = 0; c < 4; ++c) {
        __syncthreads();
        st_tile(sAh, sAl, tid, bufA);
        st_tile(sBh, sBl, tid, bufB);
        if (c < 3) {
            ld_tile(g_h + m0 * HDIM + (c + 1) * KC, HDIM, tid, bufA);
            ld_tile(g_WcatT + n0 * HDIM + (c + 1) * KC, HDIM, tid, bufB);
        }
        __syncthreads();
        chunk_mma(sAh, sAl, sBh, sBl, wm, wn, lane, acc);
    }

    // epilogue: fragments -> g_P (float2 stores, 8B aligned: cols even)
    const int g = lane >> 2, t = lane & 3;
#pragma unroll
    for (int i = 0; i < 2; ++i) {
        int r0 = m0 + wm * 32 + 16 * i + g;
#pragma unroll
        for (int j = 0; j < 8; ++j) {
            int cc = n0 + wn * 64 + 8 * j + t * 2;
            *(float2*)(g_P + r0 * PW + cc)       = make_float2(acc[i][j][0], acc[i][j][1]);
            *(float2*)(g_P + (r0 + 8) * PW + cc) = make_float2(acc[i][j][2], acc[i][j][3]);
        }
    }
}

// ---------------- skinny W_w projections (runs right after gemm1: L2-hot) --
__global__ __launch_bounds__(256)
void k_ww(const float* __restrict__ Ww) {
    int wid = threadIdx.x >> 5, lane = threadIdx.x & 31;
    int m = blockIdx.x * 8 + wid;               // grid = 1024
    const float* hrow = g_h + m * HDIM;
    float s0 = 0.f, s1 = 0.f;
#pragma unroll
    for (int it = 0; it < 2; ++it) {
        int k = it * 128 + lane * 4;
        float4 hv = *(const float4*)(hrow + k);
        float4 w0 = *(const float4*)(Ww + k);
        float4 w1 = *(const float4*)(Ww + HDIM + k);
        s0 += hv.x * w0.x + hv.y * w0.y + hv.z * w0.z + hv.w * w0.w;
        s1 += hv.x * w1.x + hv.y * w1.y + hv.z * w1.z + hv.w * w1.w;
    }
#pragma unroll
    for (int o = 16; o; o >>= 1) {
        s0 += __shfl_down_sync(0xffffffffu, s0, o);
        s1 += __shfl_down_sync(0xffffffffu, s1, o);
    }
    if (lane == 0) { g_Pw[m * 2] = s0; g_Pw[m * 2 + 1] = s1; }
}

// ---------------- per-edge pass: sim * exp(logit), partial sums ------------
__device__ __forceinline__ float edge_term(float m, float t) {
    float sp = fmaxf(t, 0.f) + __logf(1.f + __expf(-fabsf(t)));
    return __fdividef(m * m, sp + 1.01e-6f);   // 1e-6 (softplus eps) + 1e-8 (sim eps)
}

__global__ __launch_bounds__(512)
void k_edges(const float* __restrict__ bm, const float* __restrict__ bv,
             const float* __restrict__ bw, const float* __restrict__ gum) {
    extern __shared__ float sP[];               // 64 * 532 floats, biases folded in
    __shared__ float sW[128], red[512];
    const int b = blockIdx.x, tid = threadIdx.x;

    const float* src = g_P + b * (NNODE * PW);
    for (int idx = tid; idx < NNODE * PW; idx += 512) {
        int n = idx >> 9, c = idx & 511;
        float add = 0.f;
        if (c < 128)                  add = __ldg(bm + c);
        else if (c >= 256 && c < 384) add = __ldg(bv + (c - 256));
        sP[n * PSTR + c] = src[idx] + add;
    }
    if (tid < 128) sW[tid] = g_Pw[b * 128 + tid];
    const float bww = bw[0];
    __syncthreads();

    float lsum = 0.f;
    for (int e = tid; e < EPG; e += 512) {
        // invert triangular index: base(i) = i*63 - i*(i-1)/2
        int i = (int)((127.0f - sqrtf((float)(16129 - 8 * e))) * 0.5f);
        while ((i + 1) * 63 - ((i + 1) * i) / 2 <= e) ++i;
        while (i * 63 - (i * (i - 1)) / 2 > e)        --i;
        int base = i * 63 - (i * (i - 1)) / 2;
        int j = e - base + i + 1;

        const float* ps = sP + i * PSTR;
        const float* pd = sP + j * PSTR;
        float acc = 0.f;
#pragma unroll 4
        for (int k = 0; k < ODIM; k += 4) {
            float4 a  = *(const float4*)(ps + k);           // mean src + bm
            float4 bb = *(const float4*)(pd + 128 + k);     // mean dst
            float4 cs = *(const float4*)(ps + 256 + k);     // var  src + bv
            float4 dd = *(const float4*)(pd + 384 + k);     // var  dst
            acc += edge_term(a.x + bb.x, cs.x + dd.x);
            acc += edge_term(a.y + bb.y, cs.y + dd.y);
            acc += edge_term(a.z + bb.z, cs.z + dd.z);
            acc += edge_term(a.w + bb.w, cs.w + dd.w);
        }
        float sim = __expf(acc * (-1.0f / 256.0f));         // exp(-0.5*mean)
        float wl  = sW[2 * i] + sW[2 * j + 1] + bww;
        float w   = __fdividef(1.f, 1.f + __expf(-wl));
        float u   = gum[b * EPG + e];
        float gmb = -__logf(-logf(u));
        float num = __expf((w + gmb) * 2.0f);               // /TEMPERATURE(0.5)
        g_simnum[b * EPG + e] = sim * num;
        lsum += num;
    }
    red[tid] = lsum;
    __syncthreads();
    for (int s2 = 256; s2 > 0; s2 >>= 1) {
        if (tid < s2) red[tid] += red[tid + s2];
        __syncthreads();
    }
    if (tid == 0) g_partials[b] = red[0];
}

// ---------------- fused reduce + scatter to dense adjacency ----------------
__global__ __launch_bounds__(256)
void k_final(float* __restrict__ out) {
    __shared__ float red[128];
    const int tid = threadIdx.x;
    if (tid < 128) red[tid] = g_partials[tid];
    __syncthreads();
    for (int s = 64; s > 0; s >>= 1) {
        if (tid < s) red[tid] += red[tid + s];
        __syncthreads();
    }
    const float invS = 1.0f / red[0];

    int base = (blockIdx.x * 256 + tid) * 4;    // 4 consecutive cols, same row
    int b = base >> 12;
    int r = (base >> 6) & 63;
    int c = base & 63;
    float v[4];
#pragma unroll
    for (int q = 0; q < 4; ++q) {
        int col = c + q;
        float x = 0.f;
        if (r < col) {
            int e = r * 63 - (r * (r - 1)) / 2 + (col - r - 1);
            x = g_simnum[b * EPG + e] * invS;
        }
        v[q] = x;
    }
    *(float4*)(out + base) = make_float4(v[0], v[1], v[2], v[3]);
}

// ---------------- launch ----------------------------------------------------
extern "C" void kernel_launch(void* const* d_in, const int* in_sizes, int n_in,
                              void* d_out, int out_size) {
    const float* topo  = (const float*)d_in[0];
    const float* temp  = (const float*)d_in[1];
    const float* gum   = (const float*)d_in[2];
    const float* Wgnn  = (const float*)d_in[3];
    const float* bgnn  = (const float*)d_in[4];
    const float* Wm    = (const float*)d_in[5];
    const float* bmn   = (const float*)d_in[6];
    const float* Wv    = (const float*)d_in[7];
    const float* bvr   = (const float*)d_in[8];
    const float* Ww    = (const float*)d_in[9];
    const float* bww   = (const float*)d_in[10];
    float* out = (float*)d_out;

    static bool init_done = false;
    if (!init_done) {
        cudaFuncSetAttribute(gemm1_mma, cudaFuncAttributeMaxDynamicSharedMemorySize, MM_SMEM);
        cudaFuncSetAttribute(gemm2_mma, cudaFuncAttributeMaxDynamicSharedMemorySize, MM_SMEM);
        cudaFuncSetAttribute(k_edges,   cudaFuncAttributeMaxDynamicSharedMemorySize, ED_SMEM);
        init_done = true;
    }

    // 1. transpose/pack weights
    k_prep_T<<<(HDIM * KIN + PW * HDIM + 255) / 256, 256>>>(Wgnn, Wm, Wv);

    // 2. h = relu(prefixmean(xcat @ Wgnn) + b)  — pipelined mma, fused scan
    gemm1_mma<<<dim3(HDIM / 128, MROWS / 128), 256, MM_SMEM>>>(topo, temp, bgnn);

    // 3. skinny W_w projections (g_h still L2-resident)
    k_ww<<<MROWS / 8, 256>>>(Ww);

    // 4. P = h @ Wcat  — pipelined mma
    gemm2_mma<<<dim3(PW / 128, MROWS / 128), 256, MM_SMEM>>>();

    // 5. per-edge sim * exp(logit), block partial sums
    k_edges<<<BATCH, 512, ED_SMEM>>>(bmn, bvr, bww, gum);

    // 6. fused global-sum + dense adjacency scatter
    k_final<<<(BATCH * NNODE * NNODE) / (256 * 4), 256>>>(out);
}

// round 10
// speedup vs baseline: 1.0021x; 1.0021x over previous
#include <cuda_runtime.h>
#include <cuda_bf16.h>
#include <math.h>
#include <cstdint>

// Problem constants
#define BATCH   128
#define NNODE   64
#define TDIM    256
#define KIN     320          // N + T
#define HDIM    256
#define ODIM    128
#define EPG     2016         // edges per graph
#define TEDGE   (BATCH*EPG)  // 258048
#define MROWS   (BATCH*NNODE)// 8192
#define PW      512          // packed mean/var head width
#define PSTR    532          // smem row stride (x4B: 2128B; mod 128B = 80 -> conflict-free LDS.128)

// mma staging: k-chunk 64, row stride 36 b32 (144B: mod 128 = 16 -> conflict-free LDSM)
#define KC      64
#define BSTR    36           // b32 per staged row
#define REG_U32 (128 * BSTR) // 4608 u32 per tile region
#define MM_SMEM (4 * REG_U32 * 4)  // 73728 bytes
#define ED_SMEM (NNODE * PSTR * 4) // 136192 bytes

// ---------------- device scratch (static, allocation-free) ----------------
__device__ float g_h     [MROWS * HDIM];   //  8.4 MB
__device__ float g_WgnnT [HDIM * KIN];     //  0.33 MB  (Wgnn^T: [256][320])
__device__ float g_WcatT [PW * HDIM];      //  0.52 MB  (packed heads^T: [512][256])
__device__ float g_P     [MROWS * PW];     // 16.8 MB
__device__ float g_Pw    [MROWS * 2];      //  64 KB
__device__ float g_simnum[TEDGE];          //  1.0 MB
__device__ float g_partials[BATCH];

// ==================== mma.sync + ldmatrix helpers (sm_75+/80+ PTX) =========
__device__ __forceinline__ void mma_bf16(float* c, const uint32_t* a, const uint32_t* b) {
    asm volatile(
        "mma.sync.aligned.m16n8k16.row.col.f32.bf16.bf16.f32 "
        "{%0,%1,%2,%3}, {%4,%5,%6,%7}, {%8,%9}, {%0,%1,%2,%3};"
        : "+f"(c[0]), "+f"(c[1]), "+f"(c[2]), "+f"(c[3])
        : "r"(a[0]), "r"(a[1]), "r"(a[2]), "r"(a[3]), "r"(b[0]), "r"(b[1]));
}
__device__ __forceinline__ void ldsm4(uint32_t addr, uint32_t* r) {
    asm volatile("ldmatrix.sync.aligned.m8n8.x4.shared.b16 {%0,%1,%2,%3}, [%4];"
                 : "=r"(r[0]), "=r"(r[1]), "=r"(r[2]), "=r"(r[3]) : "r"(addr));
}
__device__ __forceinline__ uint32_t smem_u32(const void* p) {
    uint32_t a;
    asm("{ .reg .u64 t; cvta.to.shared.u64 t, %1; cvt.u32.u64 %0, t; }" : "=r"(a) : "l"(p));
    return a;
}

// split two floats into packed bf16x2 hi and lo (low 16 bits = first element)
__device__ __forceinline__ void cvt2(float a, float b, uint32_t& hi, uint32_t& lo) {
    __nv_bfloat16 ha = __float2bfloat16_rn(a), hb = __float2bfloat16_rn(b);
    float ra = a - __bfloat162float(ha), rb = b - __bfloat162float(hb);
    __nv_bfloat16 la = __float2bfloat16_rn(ra), lb = __float2bfloat16_rn(rb);
    hi = ((uint32_t)__bfloat16_as_ushort(hb) << 16) | (uint32_t)__bfloat16_as_ushort(ha);
    lo = ((uint32_t)__bfloat16_as_ushort(lb) << 16) | (uint32_t)__bfloat16_as_ushort(la);
}

// stage 128 rows x 64 f32 cols -> hi/lo bf16x2 tiles [128][BSTR u32]
__device__ __forceinline__ void stage64(const float* __restrict__ g, int gstride,
                                        uint32_t* __restrict__ sh,
                                        uint32_t* __restrict__ sl, int tid) {
    const int row = tid >> 1, cg = (tid & 1) * 16;      // 16 b32 = 32 floats
    const float* src = g + row * gstride + cg * 2;
    uint32_t* dh = sh + row * BSTR + cg;
    uint32_t* dl = sl + row * BSTR + cg;
#pragma unroll
    for (int q = 0; q < 8; ++q) {
        float4 v = *(const float4*)(src + q * 4);
        uint32_t h0, l0, h1, l1;
        cvt2(v.x, v.y, h0, l0);
        cvt2(v.z, v.w, h1, l1);
        dh[2 * q] = h0; dh[2 * q + 1] = h1;
        dl[2 * q] = l0; dl[2 * q + 1] = l1;
    }
}

// one k=64 chunk of bf16x2-compensated mma via ldmatrix, into acc[2][8][4]
// Regions passed as u32 smem byte addresses.
__device__ __forceinline__ void chunk_mma(uint32_t bAh, uint32_t bAl,
                                          uint32_t bBh, uint32_t bBl,
                                          int wm, int wn, int lane,
                                          float acc[2][8][4]) {
    const int grp = lane >> 3, rig = lane & 7;   // ldmatrix: 4 groups of 8 addr threads
#pragma unroll
    for (int kb = 0; kb < 4; ++kb) {
        uint32_t Ah[2][4], Al[2][4], Bh[8][2], Bl[8][2];
        // A: m16k16 per ldsm.x4 — grp0: r0-7 klo, grp1: r8-15 klo, grp2: r0-7 khi, grp3: r8-15 khi
#pragma unroll
        for (int i = 0; i < 2; ++i) {
            uint32_t off = (uint32_t)((wm * 32 + i * 16 + (grp & 1) * 8 + rig) * (BSTR * 4)
                                      + (kb * 16 + (grp >> 1) * 8) * 2);
            ldsm4(bAh + off, Ah[i]);
            ldsm4(bAl + off, Al[i]);
        }
        // B: two n8-tiles per ldsm.x4 — grp0: n(2jj) klo, grp1: n(2jj) khi, grp2: n(2jj+1) klo, grp3: khi
#pragma unroll
        for (int jj = 0; jj < 4; ++jj) {
            uint32_t off = (uint32_t)((wn * 64 + jj * 16 + (grp >> 1) * 8 + rig) * (BSTR * 4)
                                      + (kb * 16 + (grp & 1) * 8) * 2);
            ldsm4(bBh + off, &Bh[2 * jj][0]);
            ldsm4(bBl + off, &Bl[2 * jj][0]);
        }
#pragma unroll
        for (int i = 0; i < 2; ++i)
#pragma unroll
            for (int j = 0; j < 8; ++j) {
                mma_bf16(acc[i][j], Ah[i], Bh[j]);   // hi*hi
                mma_bf16(acc[i][j], Ah[i], Bl[j]);   // hi*lo
                mma_bf16(acc[i][j], Al[i], Bh[j]);   // lo*hi
            }
    }
}

// ---------------- prep: transpose Wgnn + pack/transpose heads --------------
__global__ void k_prep_T(const float* __restrict__ Wgnn, const float* __restrict__ Wm,
                         const float* __restrict__ Wv) {
    int idx = blockIdx.x * blockDim.x + threadIdx.x;
    if (idx < HDIM * KIN) {
        int n = idx / KIN, k = idx - n * KIN;
        g_WgnnT[idx] = Wgnn[k * HDIM + n];
        return;
    }
    idx -= HDIM * KIN;
    if (idx >= PW * HDIM) return;
    int n = idx >> 8, k = idx & 255;
    float v;
    if      (n < 128) v = Wm[k * ODIM + n];
    else if (n < 256) v = Wm[(HDIM + k) * ODIM + (n - 128)];
    else if (n < 384) v = Wv[k * ODIM + (n - 256)];
    else              v = Wv[(HDIM + k) * ODIM + (n - 384)];
    g_WcatT[idx] = v;
}

// ====== GEMM1 (mma.sync bf16x2 + ldmatrix): h = relu(prefixmean(..)+b) =====
// grid (2, 64), 256 threads. K=320 in 5 chunks of 64. Fused scan epilogue.
__global__ __launch_bounds__(256)
void gemm1_mma(const float* __restrict__ topo, const float* __restrict__ temp,
               const float* __restrict__ bias) {
    extern __shared__ uint32_t sm[];
    uint32_t *sAh = sm, *sAl = sm + REG_U32, *sBh = sm + 2 * REG_U32, *sBl = sm + 3 * REG_U32;
    const uint32_t smb = smem_u32(sm);
    const uint32_t bAh = smb, bAl = smb + REG_U32 * 4, bBh = smb + 2 * REG_U32 * 4, bBl = smb + 3 * REG_U32 * 4;
    const int tid = threadIdx.x, lane = tid & 31, wid = tid >> 5;
    const int wm = wid >> 1, wn = wid & 1;
    const int bx = blockIdx.x, by = blockIdx.y;
    const int m0 = by * 128, n0 = bx * 128;

    float acc[2][8][4];
#pragma unroll
    for (int i = 0; i < 2; ++i)
#pragma unroll
        for (int j = 0; j < 8; ++j)
#pragma unroll
            for (int q = 0; q < 4; ++q) acc[i][j][q] = 0.f;

#pragma unroll 1
    for (int c = 0; c < 5; ++c) {
        __syncthreads();
        if (c == 0) stage64(topo + m0 * NNODE, NNODE, sAh, sAl, tid);
        else        stage64(temp + m0 * TDIM + (c - 1) * KC, TDIM, sAh, sAl, tid);
        stage64(g_WgnnT + n0 * KIN + c * KC, KIN, sBh, sBl, tid);
        __syncthreads();
        chunk_mma(bAh, bAl, bBh, bBl, wm, wn, lane, acc);
    }

    // epilogue: fragments -> smem scan buffer (aliased over staging tiles)
    __syncthreads();
    float* sD = (float*)sm;                 // 128 x 129 floats (66 KB <= 72 KB)
    const int g = lane >> 2, t = lane & 3;
#pragma unroll
    for (int i = 0; i < 2; ++i) {
        int r0 = wm * 32 + 16 * i + g;
#pragma unroll
        for (int j = 0; j < 8; ++j) {
            int cc = wn * 64 + 8 * j + t * 2;
            sD[r0 * 129 + cc]       = acc[i][j][0];
            sD[r0 * 129 + cc + 1]   = acc[i][j][1];
            sD[(r0 + 8) * 129 + cc]     = acc[i][j][2];
            sD[(r0 + 8) * 129 + cc + 1] = acc[i][j][3];
        }
    }
    __syncthreads();

    // prefix-mean + ReLU: 256 threads = 128 cols x 2 graphs
    {
        const int col = tid & 127, gph = tid >> 7;
        const float bv = bias[n0 + col];
        float s = 0.f;
        float* hout = g_h + ((by * 2 + gph) * NNODE) * HDIM + n0 + col;
#pragma unroll 4
        for (int j = 0; j < NNODE; ++j) {
            float agg = (j > 0) ? (s / (float)j) : 0.f;
            hout[j * HDIM] = fmaxf(agg + bv, 0.f);
            s += sD[(gph * NNODE + j) * 129 + col];
        }
    }
}

// ====== GEMM2 (mma.sync bf16x2 + ldmatrix): P = h @ WcatT^T ================
// grid (4, 64), 256 threads, 2 CTAs/SM -> single wave. K=256 in 4 chunks.
__global__ __launch_bounds__(256, 2)
void gemm2_mma() {
    extern __shared__ uint32_t sm[];
    uint32_t *sAh = sm, *sAl = sm + REG_U32, *sBh = sm + 2 * REG_U32, *sBl = sm + 3 * REG_U32;
    const uint32_t smb = smem_u32(sm);
    const uint32_t bAh = smb, bAl = smb + REG_U32 * 4, bBh = smb + 2 * REG_U32 * 4, bBl = smb + 3 * REG_U32 * 4;
    const int tid = threadIdx.x, lane = tid & 31, wid = tid >> 5;
    const int wm = wid >> 1, wn = wid & 1;
    const int bx = blockIdx.x, by = blockIdx.y;
    const int m0 = by * 128, n0 = bx * 128;

    float acc[2][8][4];
#pragma unroll
    for (int i = 0; i < 2; ++i)
#pragma unroll
        for (int j = 0; j < 8; ++j)
#pragma unroll
            for (int q = 0; q < 4; ++q) acc[i][j][q] = 0.f;

#pragma unroll 1
    for (int c = 0; c < 4; ++c) {
        __syncthreads();
        stage64(g_h + m0 * HDIM + c * KC, HDIM, sAh, sAl, tid);
        stage64(g_WcatT + n0 * HDIM + c * KC, HDIM, sBh, sBl, tid);
        __syncthreads();
        chunk_mma(bAh, bAl, bBh, bBl, wm, wn, lane, acc);
    }

    // epilogue: fragments -> g_P (float2 stores, 8B aligned: cols even)
    const int g = lane >> 2, t = lane & 3;
#pragma unroll
    for (int i = 0; i < 2; ++i) {
        int r0 = m0 + wm * 32 + 16 * i + g;
#pragma unroll
        for (int j = 0; j < 8; ++j) {
            int cc = n0 + wn * 64 + 8 * j + t * 2;
            *(float2*)(g_P + r0 * PW + cc)       = make_float2(acc[i][j][0], acc[i][j][1]);
            *(float2*)(g_P + (r0 + 8) * PW + cc) = make_float2(acc[i][j][2], acc[i][j][3]);
        }
    }
}

// ---------------- skinny W_w projections (runs right after gemm1: L2-hot) --
__global__ __launch_bounds__(256)
void k_ww(const float* __restrict__ Ww) {
    int wid = threadIdx.x >> 5, lane = threadIdx.x & 31;
    int m = blockIdx.x * 8 + wid;               // grid = 1024
    const float* hrow = g_h + m * HDIM;
    float s0 = 0.f, s1 = 0.f;
#pragma unroll
    for (int it = 0; it < 2; ++it) {
        int k = it * 128 + lane * 4;
        float4 hv = *(const float4*)(hrow + k);
        float4 w0 = *(const float4*)(Ww + k);
        float4 w1 = *(const float4*)(Ww + HDIM + k);
        s0 += hv.x * w0.x + hv.y * w0.y + hv.z * w0.z + hv.w * w0.w;
        s1 += hv.x * w1.x + hv.y * w1.y + hv.z * w1.z + hv.w * w1.w;
    }
#pragma unroll
    for (int o = 16; o; o >>= 1) {
        s0 += __shfl_down_sync(0xffffffffu, s0, o);
        s1 += __shfl_down_sync(0xffffffffu, s1, o);
    }
    if (lane == 0) { g_Pw[m * 2] = s0; g_Pw[m * 2 + 1] = s1; }
}

// ---------------- per-edge pass: sim * exp(logit), partial sums ------------
__device__ __forceinline__ float edge_term(float m, float t) {
    float sp = fmaxf(t, 0.f) + __logf(1.f + __expf(-fabsf(t)));
    return __fdividef(m * m, sp + 1.01e-6f);   // 1e-6 (softplus eps) + 1e-8 (sim eps)
}

__global__ __launch_bounds__(512)
void k_edges(const float* __restrict__ bm, const float* __restrict__ bv,
             const float* __restrict__ bw, const float* __restrict__ gum) {
    extern __shared__ float sP[];               // 64 * 532 floats, biases folded in
    __shared__ float sW[128], red[512];
    const int b = blockIdx.x, tid = threadIdx.x;

    const float* src = g_P + b * (NNODE * PW);
    for (int idx = tid; idx < NNODE * PW; idx += 512) {
        int n = idx >> 9, c = idx & 511;
        float add = 0.f;
        if (c < 128)                  add = __ldg(bm + c);
        else if (c >= 256 && c < 384) add = __ldg(bv + (c - 256));
        sP[n * PSTR + c] = src[idx] + add;
    }
    if (tid < 128) sW[tid] = g_Pw[b * 128 + tid];
    const float bww = bw[0];
    __syncthreads();

    float lsum = 0.f;
    for (int e = tid; e < EPG; e += 512) {
        // invert triangular index: base(i) = i*63 - i*(i-1)/2
        int i = (int)((127.0f - sqrtf((float)(16129 - 8 * e))) * 0.5f);
        while ((i + 1) * 63 - ((i + 1) * i) / 2 <= e) ++i;
        while (i * 63 - (i * (i - 1)) / 2 > e)        --i;
        int base = i * 63 - (i * (i - 1)) / 2;
        int j = e - base + i + 1;

        const float* ps = sP + i * PSTR;
        const float* pd = sP + j * PSTR;
        float acc = 0.f;
#pragma unroll 4
        for (int k = 0; k < ODIM; k += 4) {
            float4 a  = *(const float4*)(ps + k);           // mean src + bm
            float4 bb = *(const float4*)(pd + 128 + k);     // mean dst
            float4 cs = *(const float4*)(ps + 256 + k);     // var  src + bv
            float4 dd = *(const float4*)(pd + 384 + k);     // var  dst
            acc += edge_term(a.x + bb.x, cs.x + dd.x);
            acc += edge_term(a.y + bb.y, cs.y + dd.y);
            acc += edge_term(a.z + bb.z, cs.z + dd.z);
            acc += edge_term(a.w + bb.w, cs.w + dd.w);
        }
        float sim = __expf(acc * (-1.0f / 256.0f));         // exp(-0.5*mean)
        float wl  = sW[2 * i] + sW[2 * j + 1] + bww;
        float w   = __fdividef(1.f, 1.f + __expf(-wl));
        float u   = gum[b * EPG + e];
        float gmb = -__logf(-logf(u));
        float num = __expf((w + gmb) * 2.0f);               // /TEMPERATURE(0.5)
        g_simnum[b * EPG + e] = sim * num;
        lsum += num;
    }
    red[tid] = lsum;
    __syncthreads();
    for (int s2 = 256; s2 > 0; s2 >>= 1) {
        if (tid < s2) red[tid] += red[tid + s2];
        __syncthreads();
    }
    if (tid == 0) g_partials[b] = red[0];
}

// ---------------- fused reduce + scatter to dense adjacency ----------------
__global__ __launch_bounds__(256)
void k_final(float* __restrict__ out) {
    __shared__ float red[128];
    const int tid = threadIdx.x;
    if (tid < 128) red[tid] = g_partials[tid];
    __syncthreads();
    for (int s = 64; s > 0; s >>= 1) {
        if (tid < s) red[tid] += red[tid + s];
        __syncthreads();
    }
    const float invS = 1.0f / red[0];

    int base = (blockIdx.x * 256 + tid) * 4;    // 4 consecutive cols, same row
    int b = base >> 12;
    int r = (base >> 6) & 63;
    int c = base & 63;
    float v[4];
#pragma unroll
    for (int q = 0; q < 4; ++q) {
        int col = c + q;
        float x = 0.f;
        if (r < col) {
            int e = r * 63 - (r * (r - 1)) / 2 + (col - r - 1);
            x = g_simnum[b * EPG + e] * invS;
        }
        v[q] = x;
    }
    *(float4*)(out + base) = make_float4(v[0], v[1], v[2], v[3]);
}

// ---------------- launch ----------------------------------------------------
extern "C" void kernel_launch(void* const* d_in, const int* in_sizes, int n_in,
                              void* d_out, int out_size) {
    const float* topo  = (const float*)d_in[0];
    const float* temp  = (const float*)d_in[1];
    const float* gum   = (const float*)d_in[2];
    const float* Wgnn  = (const float*)d_in[3];
    const float* bgnn  = (const float*)d_in[4];
    const float* Wm    = (const float*)d_in[5];
    const float* bmn   = (const float*)d_in[6];
    const float* Wv    = (const float*)d_in[7];
    const float* bvr   = (const float*)d_in[8];
    const float* Ww    = (const float*)d_in[9];
    const float* bww   = (const float*)d_in[10];
    float* out = (float*)d_out;

    static bool init_done = false;
    if (!init_done) {
        cudaFuncSetAttribute(gemm1_mma, cudaFuncAttributeMaxDynamicSharedMemorySize, MM_SMEM);
        cudaFuncSetAttribute(gemm2_mma, cudaFuncAttributeMaxDynamicSharedMemorySize, MM_SMEM);
        cudaFuncSetAttribute(k_edges,   cudaFuncAttributeMaxDynamicSharedMemorySize, ED_SMEM);
        init_done = true;
    }

    // 1. transpose/pack weights
    k_prep_T<<<(HDIM * KIN + PW * HDIM + 255) / 256, 256>>>(Wgnn, Wm, Wv);

    // 2. h = relu(prefixmean(xcat @ Wgnn) + b)  — ldmatrix mma, fused scan
    gemm1_mma<<<dim3(HDIM / 128, MROWS / 128), 256, MM_SMEM>>>(topo, temp, bgnn);

    // 3. skinny W_w projections (g_h still L2-resident)
    k_ww<<<MROWS / 8, 256>>>(Ww);

    // 4. P = h @ Wcat  — ldmatrix mma, 2 CTAs/SM
    gemm2_mma<<<dim3(PW / 128, MROWS / 128), 256, MM_SMEM>>>();

    // 5. per-edge sim * exp(logit), block partial sums
    k_edges<<<BATCH, 512, ED_SMEM>>>(bmn, bvr, bww, gum);

    // 6. fused global-sum + dense adjacency scatter
    k_final<<<(BATCH * NNODE * NNODE) / (256 * 4), 256>>>(out);
}

// round 12
// speedup vs baseline: 1.1361x; 1.1337x over previous
#include <cuda_runtime.h>
#include <cuda_bf16.h>
#include <math.h>
#include <cstdint>

// Problem constants
#define BATCH   128
#define NNODE   64
#define TDIM    256
#define KIN     320          // N + T
#define HDIM    256
#define ODIM    128
#define EPG     2016         // edges per graph
#define TEDGE   (BATCH*EPG)  // 258048
#define MROWS   (BATCH*NNODE)// 8192
#define PW      512          // packed mean/var head width
#define PSTR    532          // smem row stride in edge kernel (conflict-free LDS.128)

// staged region geometry: rows of 64 bf16 (128B), row stride 144B (conflict-free LDSM)
#define RSTRB   144
#define RB_A    18432        // 128 rows * 144B
#define RB_B2   36864        // 256 rows * 144B
#define BUF1    (4 * RB_A)             // 73728  (gemm1: Ah,Al,Bh,Bl @128 rows)
#define SMEM1   (2 * BUF1)             // 147456
#define BUF2    (2 * RB_A + 2 * RB_B2) // 110592 (gemm2: A@128, B@256 rows)
#define SMEM2   (2 * BUF2)             // 221184
#define ED_SMEM (NNODE * PSTR * 4)     // 136192

// ---------------- device scratch (static, allocation-free) ----------------
__device__ __align__(16) __nv_bfloat16 g_xh [MROWS * KIN];   // x_cat hi
__device__ __align__(16) __nv_bfloat16 g_xl [MROWS * KIN];   // x_cat lo
__device__ __align__(16) __nv_bfloat16 g_Wgh[HDIM * KIN];    // WgnnT hi
__device__ __align__(16) __nv_bfloat16 g_Wgl[HDIM * KIN];    // WgnnT lo
__device__ __align__(16) __nv_bfloat16 g_hh [MROWS * HDIM];  // h hi
__device__ __align__(16) __nv_bfloat16 g_hl [MROWS * HDIM];  // h lo
__device__ __align__(16) __nv_bfloat16 g_Wch[PW * HDIM];     // Wcat^T hi
__device__ __align__(16) __nv_bfloat16 g_Wcl[PW * HDIM];     // Wcat^T lo
__device__ float g_P     [MROWS * PW];         // 16.8 MB
__device__ float g_Pw    [MROWS * 2];
__device__ float g_simnum[TEDGE];
__device__ float g_partials[BATCH];

// ==================== PTX helpers (all baseline sm_80 PTX) =================
__device__ __forceinline__ void mma_bf16(float* c, const uint32_t* a, const uint32_t* b) {
    asm volatile(
        "mma.sync.aligned.m16n8k16.row.col.f32.bf16.bf16.f32 "
        "{%0,%1,%2,%3}, {%4,%5,%6,%7}, {%8,%9}, {%0,%1,%2,%3};"
        : "+f"(c[0]), "+f"(c[1]), "+f"(c[2]), "+f"(c[3])
        : "r"(a[0]), "r"(a[1]), "r"(a[2]), "r"(a[3]), "r"(b[0]), "r"(b[1]));
}
__device__ __forceinline__ void ldsm4(uint32_t addr, uint32_t* r) {
    asm volatile("ldmatrix.sync.aligned.m8n8.x4.shared.b16 {%0,%1,%2,%3}, [%4];"
                 : "=r"(r[0]), "=r"(r[1]), "=r"(r[2]), "=r"(r[3]) : "r"(addr));
}
__device__ __forceinline__ uint32_t smem_u32(const void* p) {
    uint32_t a;
    asm("{ .reg .u64 t; cvta.to.shared.u64 t, %1; cvt.u32.u64 %0, t; }" : "=r"(a) : "l"(p));
    return a;
}
__device__ __forceinline__ void cpa16(uint32_t dst, const void* src) {
    asm volatile("cp.async.cg.shared.global [%0], [%1], 16;" :: "r"(dst), "l"(src) : "memory");
}
#define CP_COMMIT() asm volatile("cp.async.commit_group;" ::: "memory")
#define CP_WAIT1()  asm volatile("cp.async.wait_group 1;" ::: "memory")
#define CP_WAIT0()  asm volatile("cp.async.wait_group 0;" ::: "memory")

__device__ __forceinline__ void split_bf16(float v, __nv_bfloat16& h, __nv_bfloat16& l) {
    h = __float2bfloat16_rn(v);
    l = __float2bfloat16_rn(v - __bfloat162float(h));
}

// one k=64 chunk of bf16x2-compensated mma via ldmatrix, into acc[2][8][4]
__device__ __forceinline__ void chunk_mma(uint32_t bAh, uint32_t bAl,
                                          uint32_t bBh, uint32_t bBl,
                                          int wm, int wn, int lane,
                                          float acc[2][8][4]) {
    const int grp = lane >> 3, rig = lane & 7;
#pragma unroll
    for (int kb = 0; kb < 4; ++kb) {
        uint32_t Ah[2][4], Al[2][4], Bh[8][2], Bl[8][2];
#pragma unroll
        for (int i = 0; i < 2; ++i) {
            uint32_t off = (uint32_t)((wm * 32 + i * 16 + (grp & 1) * 8 + rig) * RSTRB
                                      + (kb * 16 + (grp >> 1) * 8) * 2);
            ldsm4(bAh + off, Ah[i]);
            ldsm4(bAl + off, Al[i]);
        }
#pragma unroll
        for (int jj = 0; jj < 4; ++jj) {
            uint32_t off = (uint32_t)((wn * 64 + jj * 16 + (grp >> 1) * 8 + rig) * RSTRB
                                      + (kb * 16 + (grp & 1) * 8) * 2);
            ldsm4(bBh + off, &Bh[2 * jj][0]);
            ldsm4(bBl + off, &Bl[2 * jj][0]);
        }
#pragma unroll
        for (int i = 0; i < 2; ++i)
#pragma unroll
            for (int j = 0; j < 8; ++j) {
                mma_bf16(acc[i][j], Ah[i], Bh[j]);   // hi*hi
                mma_bf16(acc[i][j], Ah[i], Bl[j]);   // hi*lo
                mma_bf16(acc[i][j], Al[i], Bh[j]);   // lo*hi
            }
    }
}

// ---------------- prep: split x_cat / WgnnT / Wcat into bf16 hi/lo ---------
__global__ void k_prep(const float* __restrict__ topo, const float* __restrict__ temp,
                       const float* __restrict__ Wgnn, const float* __restrict__ Wm,
                       const float* __restrict__ Wv) {
    int idx = blockIdx.x * blockDim.x + threadIdx.x;
    if (idx < MROWS * KIN) {
        int m = idx / KIN, k = idx - m * KIN;
        float v = (k < NNODE) ? topo[m * NNODE + k] : temp[m * TDIM + (k - NNODE)];
        split_bf16(v, g_xh[idx], g_xl[idx]);
        return;
    }
    idx -= MROWS * KIN;
    if (idx < HDIM * KIN) {
        int n = idx / KIN, k = idx - n * KIN;
        split_bf16(Wgnn[k * HDIM + n], g_Wgh[idx], g_Wgl[idx]);
        return;
    }
    idx -= HDIM * KIN;
    if (idx >= PW * HDIM) return;
    int n = idx >> 8, k = idx & 255;
    float v;
    if      (n < 128) v = Wm[k * ODIM + n];
    else if (n < 256) v = Wm[(HDIM + k) * ODIM + (n - 128)];
    else if (n < 384) v = Wv[k * ODIM + (n - 256)];
    else              v = Wv[(HDIM + k) * ODIM + (n - 384)];
    split_bf16(v, g_Wch[idx], g_Wcl[idx]);
}

// stage one chunk (4 regions of 128 rows, stride KIN) via cp.async, 256 thr
__device__ __forceinline__ void issue1(uint32_t base, int tid,
                                       const __nv_bfloat16* __restrict__ Ah,
                                       const __nv_bfloat16* __restrict__ Al,
                                       const __nv_bfloat16* __restrict__ Bh,
                                       const __nv_bfloat16* __restrict__ Bl) {
#pragma unroll
    for (int q = 0; q < 4; ++q) {
        int idx = tid * 4 + q;
        int r = idx >> 3, ch = idx & 7;
        uint32_t d = base + r * RSTRB + ch * 16;
        int s = r * KIN + ch * 8;
        cpa16(d,            Ah + s);
        cpa16(d + RB_A,     Al + s);
        cpa16(d + 2 * RB_A, Bh + s);
        cpa16(d + 3 * RB_A, Bl + s);
    }
    CP_COMMIT();
}

// ====== GEMM1: h = relu(prefixmean(xcat@Wgnn)+b), stored as bf16 hi/lo =====
// grid (2, 64), 256 threads, double-buffered cp.async, K=320 in 5 chunks.
__global__ __launch_bounds__(256)
void gemm1_mma(const float* __restrict__ bias) {
    extern __shared__ uint32_t sm[];
    const uint32_t smb = smem_u32(sm);
    const int tid = threadIdx.x, lane = tid & 31, wid = tid >> 5;
    const int wm = wid >> 1, wn = wid & 1;
    const int bx = blockIdx.x, by = blockIdx.y;
    const int m0 = by * 128, n0 = bx * 128;

    const __nv_bfloat16 *Ah0 = g_xh + m0 * KIN,  *Al0 = g_xl + m0 * KIN;
    const __nv_bfloat16 *Bh0 = g_Wgh + n0 * KIN, *Bl0 = g_Wgl + n0 * KIN;

    float acc[2][8][4];
#pragma unroll
    for (int i = 0; i < 2; ++i)
#pragma unroll
        for (int j = 0; j < 8; ++j)
#pragma unroll
            for (int q = 0; q < 4; ++q) acc[i][j][q] = 0.f;

    issue1(smb,        tid, Ah0,      Al0,      Bh0,      Bl0);
    issue1(smb + BUF1, tid, Ah0 + 64, Al0 + 64, Bh0 + 64, Bl0 + 64);

#pragma unroll 1
    for (int c = 0; c < 5; ++c) {
        if (c < 4) CP_WAIT1(); else CP_WAIT0();
        __syncthreads();
        uint32_t b = smb + (c & 1) * BUF1;
        chunk_mma(b, b + RB_A, b + 2 * RB_A, b + 3 * RB_A, wm, wn, lane, acc);
        __syncthreads();
        if (c + 2 < 5) {
            int o = (c + 2) * 64;
            issue1(smb + (c & 1) * BUF1, tid, Ah0 + o, Al0 + o, Bh0 + o, Bl0 + o);
        }
    }

    // epilogue: fragments -> smem scan buffer (aliased over staging)
    __syncthreads();
    float* sD = (float*)sm;                 // 128 x 129 floats (66 KB)
    const int g = lane >> 2, t = lane & 3;
#pragma unroll
    for (int i = 0; i < 2; ++i) {
        int r0 = wm * 32 + 16 * i + g;
#pragma unroll
        for (int j = 0; j < 8; ++j) {
            int cc = wn * 64 + 8 * j + t * 2;
            sD[r0 * 129 + cc]           = acc[i][j][0];
            sD[r0 * 129 + cc + 1]       = acc[i][j][1];
            sD[(r0 + 8) * 129 + cc]     = acc[i][j][2];
            sD[(r0 + 8) * 129 + cc + 1] = acc[i][j][3];
        }
    }
    __syncthreads();

    // prefix-mean + ReLU + bf16 hi/lo split: 256 threads = 128 cols x 2 graphs
    {
        const int col = tid & 127, gph = tid >> 7;
        const float bv = bias[n0 + col];
        float s = 0.f;
        const int rb = ((by * 2 + gph) * NNODE) * HDIM + n0 + col;
#pragma unroll 4
        for (int j = 0; j < NNODE; ++j) {
            float agg = (j > 0) ? (s / (float)j) : 0.f;
            float hv = fmaxf(agg + bv, 0.f);
            __nv_bfloat16 hh, hl;
            split_bf16(hv, hh, hl);
            g_hh[rb + j * HDIM] = hh;
            g_hl[rb + j * HDIM] = hl;
            s += sD[(gph * NNODE + j) * 129 + col];
        }
    }
}

// stage one gemm2 chunk (A@128 rows, B@256 rows, stride HDIM), 512 thr
__device__ __forceinline__ void issue2(uint32_t base, int tid,
                                       const __nv_bfloat16* __restrict__ Ah,
                                       const __nv_bfloat16* __restrict__ Al,
                                       const __nv_bfloat16* __restrict__ Bh,
                                       const __nv_bfloat16* __restrict__ Bl) {
#pragma unroll
    for (int q = 0; q < 2; ++q) {
        int idx = tid * 2 + q;                  // 0..1023
        int r = idx >> 3, ch = idx & 7;
        uint32_t d = base + r * RSTRB + ch * 16;
        int s = r * HDIM + ch * 8;
        cpa16(d,        Ah + s);
        cpa16(d + RB_A, Al + s);
    }
#pragma unroll
    for (int q = 0; q < 4; ++q) {
        int idx = tid * 4 + q;                  // 0..2047
        int r = idx >> 3, ch = idx & 7;
        uint32_t d = base + 2 * RB_A + r * RSTRB + ch * 16;
        int s = r * HDIM + ch * 8;
        cpa16(d,         Bh + s);
        cpa16(d + RB_B2, Bl + s);
    }
    CP_COMMIT();
}

// ====== GEMM2: P = h @ Wcat^T.  grid (2,64), 512 threads, 128x256 tile =====
__global__ __launch_bounds__(512)
void gemm2_mma() {
    extern __shared__ uint32_t sm[];
    const uint32_t smb = smem_u32(sm);
    const int tid = threadIdx.x, lane = tid & 31, wid = tid >> 5;
    const int wm = wid & 3, wn = wid >> 2;      // 4 x 4 warp grid: 32x64 per warp
    const int bx = blockIdx.x, by = blockIdx.y;
    const int m0 = by * 128, n0 = bx * 256;

    const __nv_bfloat16 *Ah0 = g_hh + m0 * HDIM,  *Al0 = g_hl + m0 * HDIM;
    const __nv_bfloat16 *Bh0 = g_Wch + n0 * HDIM, *Bl0 = g_Wcl + n0 * HDIM;

    float acc[2][8][4];
#pragma unroll
    for (int i = 0; i < 2; ++i)
#pragma unroll
        for (int j = 0; j < 8; ++j)
#pragma unroll
            for (int q = 0; q < 4; ++q) acc[i][j][q] = 0.f;

    issue2(smb,        tid, Ah0,      Al0,      Bh0,      Bl0);
    issue2(smb + BUF2, tid, Ah0 + 64, Al0 + 64, Bh0 + 64, Bl0 + 64);

#pragma unroll 1
    for (int c = 0; c < 4; ++c) {
        if (c < 3) CP_WAIT1(); else CP_WAIT0();
        __syncthreads();
        uint32_t b = smb + (c & 1) * BUF2;
        chunk_mma(b, b + RB_A, b + 2 * RB_A, b + 2 * RB_A + RB_B2, wm, wn, lane, acc);
        __syncthreads();
        if (c + 2 < 4) {
            int o = (c + 2) * 64;
            issue2(smb + (c & 1) * BUF2, tid, Ah0 + o, Al0 + o, Bh0 + o, Bl0 + o);
        }
    }

    // epilogue: fragments -> g_P (float2 stores)
    const int g = lane >> 2, t = lane & 3;
#pragma unroll
    for (int i = 0; i < 2; ++i) {
        int r0 = m0 + wm * 32 + 16 * i + g;
#pragma unroll
        for (int j = 0; j < 8; ++j) {
            int cc = n0 + wn * 64 + 8 * j + t * 2;
            *(float2*)(g_P + r0 * PW + cc)       = make_float2(acc[i][j][0], acc[i][j][1]);
            *(float2*)(g_P + (r0 + 8) * PW + cc) = make_float2(acc[i][j][2], acc[i][j][3]);
        }
    }
}

// ---------------- skinny W_w projections (g_hh/g_hl L2-hot after gemm1) ----
__global__ __launch_bounds__(256)
void k_ww(const float* __restrict__ Ww) {
    int wid = threadIdx.x >> 5, lane = threadIdx.x & 31;
    int m = blockIdx.x * 8 + wid;               // grid = 1024
    int k = lane * 8;
    uint4 uh = *(const uint4*)(g_hh + m * HDIM + k);
    uint4 ul = *(const uint4*)(g_hl + m * HDIM + k);
    const __nv_bfloat16* hh = (const __nv_bfloat16*)&uh;
    const __nv_bfloat16* hl = (const __nv_bfloat16*)&ul;
    float s0 = 0.f, s1 = 0.f;
#pragma unroll
    for (int i = 0; i < 8; ++i) {
        float hv = __bfloat162float(hh[i]) + __bfloat162float(hl[i]);
        s0 += hv * __ldg(Ww + k + i);
        s1 += hv * __ldg(Ww + HDIM + k + i);
    }
#pragma unroll
    for (int o = 16; o; o >>= 1) {
        s0 += __shfl_down_sync(0xffffffffu, s0, o);
        s1 += __shfl_down_sync(0xffffffffu, s1, o);
    }
    if (lane == 0) { g_Pw[m * 2] = s0; g_Pw[m * 2 + 1] = s1; }
}

// ---------------- per-edge pass: sim * exp(logit), partial sums ------------
__device__ __forceinline__ float edge_term(float m, float t) {
    float sp = fmaxf(t, 0.f) + __logf(1.f + __expf(-fabsf(t)));
    return __fdividef(m * m, sp + 1.01e-6f);
}

__global__ __launch_bounds__(512)
void k_edges(const float* __restrict__ bm, const float* __restrict__ bv,
             const float* __restrict__ bw, const float* __restrict__ gum) {
    extern __shared__ float sP[];               // 64 * 532 floats, biases folded in
    __shared__ float sW[128], red[512];
    const int b = blockIdx.x, tid = threadIdx.x;

    const float* src = g_P + b * (NNODE * PW);
    for (int idx = tid; idx < NNODE * PW; idx += 512) {
        int n = idx >> 9, c = idx & 511;
        float add = 0.f;
        if (c < 128)                  add = __ldg(bm + c);
        else if (c >= 256 && c < 384) add = __ldg(bv + (c - 256));
        sP[n * PSTR + c] = src[idx] + add;
    }
    if (tid < 128) sW[tid] = g_Pw[b * 128 + tid];
    const float bww = bw[0];
    __syncthreads();

    float lsum = 0.f;
    for (int e = tid; e < EPG; e += 512) {
        // invert triangular index: base(i) = i*63 - i*(i-1)/2
        int i = (int)((127.0f - sqrtf((float)(16129 - 8 * e))) * 0.5f);
        while ((i + 1) * 63 - ((i + 1) * i) / 2 <= e) ++i;
        while (i * 63 - (i * (i - 1)) / 2 > e)        --i;
        int base = i * 63 - (i * (i - 1)) / 2;
        int j = e - base + i + 1;

        const float* ps = sP + i * PSTR;
        const float* pd = sP + j * PSTR;
        float acc = 0.f;
#pragma unroll 4
        for (int k = 0; k < ODIM; k += 4) {
            float4 a  = *(const float4*)(ps + k);
            float4 bb = *(const float4*)(pd + 128 + k);
            float4 cs = *(const float4*)(ps + 256 + k);
            float4 dd = *(const float4*)(pd + 384 + k);
            acc += edge_term(a.x + bb.x, cs.x + dd.x);
            acc += edge_term(a.y + bb.y, cs.y + dd.y);
            acc += edge_term(a.z + bb.z, cs.z + dd.z);
            acc += edge_term(a.w + bb.w, cs.w + dd.w);
        }
        float sim = __expf(acc * (-1.0f / 256.0f));
        float wl  = sW[2 * i] + sW[2 * j + 1] + bww;
        float w   = __fdividef(1.f, 1.f + __expf(-wl));
        float u   = gum[b * EPG + e];
        float gmb = -__logf(-logf(u));      // inner log FULL precision (see R11 post-mortem)
        float num = __expf((w + gmb) * 2.0f);
        g_simnum[b * EPG + e] = sim * num;
        lsum += num;
    }
    red[tid] = lsum;
    __syncthreads();
    for (int s2 = 256; s2 > 0; s2 >>= 1) {
        if (tid < s2) red[tid] += red[tid + s2];
        __syncthreads();
    }
    if (tid == 0) g_partials[b] = red[0];
}

// ---------------- fused reduce + scatter to dense adjacency ----------------
__global__ __launch_bounds__(256)
void k_final(float* __restrict__ out) {
    __shared__ float red[128];
    const int tid = threadIdx.x;
    if (tid < 128) red[tid] = g_partials[tid];
    __syncthreads();
    for (int s = 64; s > 0; s >>= 1) {
        if (tid < s) red[tid] += red[tid + s];
        __syncthreads();
    }
    const float invS = 1.0f / red[0];

    int base = (blockIdx.x * 256 + tid) * 4;
    int b = base >> 12;
    int r = (base >> 6) & 63;
    int c = base & 63;
    float v[4];
#pragma unroll
    for (int q = 0; q < 4; ++q) {
        int col = c + q;
        float x = 0.f;
        if (r < col) {
            int e = r * 63 - (r * (r - 1)) / 2 + (col - r - 1);
            x = g_simnum[b * EPG + e] * invS;
        }
        v[q] = x;
    }
    *(float4*)(out + base) = make_float4(v[0], v[1], v[2], v[3]);
}

// ---------------- launch ----------------------------------------------------
extern "C" void kernel_launch(void* const* d_in, const int* in_sizes, int n_in,
                              void* d_out, int out_size) {
    const float* topo  = (const float*)d_in[0];
    const float* temp  = (const float*)d_in[1];
    const float* gum   = (const float*)d_in[2];
    const float* Wgnn  = (const float*)d_in[3];
    const float* bgnn  = (const float*)d_in[4];
    const float* Wm    = (const float*)d_in[5];
    const float* bmn   = (const float*)d_in[6];
    const float* Wv    = (const float*)d_in[7];
    const float* bvr   = (const float*)d_in[8];
    const float* Ww    = (const float*)d_in[9];
    const float* bww   = (const float*)d_in[10];
    float* out = (float*)d_out;

    static bool init_done = false;
    if (!init_done) {
        cudaFuncSetAttribute(gemm1_mma, cudaFuncAttributeMaxDynamicSharedMemorySize, SMEM1);
        cudaFuncSetAttribute(gemm2_mma, cudaFuncAttributeMaxDynamicSharedMemorySize, SMEM2);
        cudaFuncSetAttribute(k_edges,   cudaFuncAttributeMaxDynamicSharedMemorySize, ED_SMEM);
        init_done = true;
    }

    const int prep_n = MROWS * KIN + HDIM * KIN + PW * HDIM;

    // 1. split inputs/weights into bf16 hi/lo
    k_prep<<<(prep_n + 255) / 256, 256>>>(topo, temp, Wgnn, Wm, Wv);

    // 2. h = relu(prefixmean(xcat @ Wgnn) + b) -> bf16 hi/lo (cp.async pipeline)
    gemm1_mma<<<dim3(2, MROWS / 128), 256, SMEM1>>>(bgnn);

    // 3. skinny W_w projections (h L2-resident)
    k_ww<<<MROWS / 8, 256>>>(Ww);

    // 4. P = h @ Wcat  (cp.async pipeline, 128x256 tiles, single wave)
    gemm2_mma<<<dim3(2, MROWS / 128), 512, SMEM2>>>();

    // 5. per-edge sim * exp(logit), block partial sums
    k_edges<<<BATCH, 512, ED_SMEM>>>(bmn, bvr, bww, gum);

    // 6. fused global-sum + dense adjacency scatter
    k_final<<<(BATCH * NNODE * NNODE) / (256 * 4), 256>>>(out);
}

// round 13
// speedup vs baseline: 1.1364x; 1.0003x over previous
#include <cuda_runtime.h>
#include <cuda_bf16.h>
#include <math.h>
#include <cstdint>

// Problem constants
#define BATCH   128
#define NNODE   64
#define TDIM    256
#define KIN     320          // N + T
#define HDIM    256
#define ODIM    128
#define EPG     2016         // edges per graph
#define TEDGE   (BATCH*EPG)  // 258048
#define MROWS   (BATCH*NNODE)// 8192
#define PW      512          // packed mean/var head width
#define PSTR    532          // smem row stride in edge kernel (conflict-free LDS.128)

// staged region geometry: rows of 64 bf16 (128B), row stride 144B (conflict-free LDSM)
#define RSTRB   144
#define RB_A    18432        // 128 rows * 144B
#define RB_B2   36864        // 256 rows * 144B
#define BUF1    (4 * RB_A)             // 73728  (gemm1: Ah,Al,Bh,Bl @128 rows)
#define SMEM1   (2 * BUF1)             // 147456
#define BUF2    (2 * RB_A + 2 * RB_B2) // 110592 (gemm2: A@128, B@256 rows)
#define SMEM2   (2 * BUF2)             // 221184
#define ED_SMEM (NNODE * PSTR * 4)     // 136192

// ---------------- device scratch (static, allocation-free) ----------------
__device__ __align__(16) __nv_bfloat16 g_xh [MROWS * KIN];   // x_cat hi
__device__ __align__(16) __nv_bfloat16 g_xl [MROWS * KIN];   // x_cat lo
__device__ __align__(16) __nv_bfloat16 g_Wgh[HDIM * KIN];    // WgnnT hi
__device__ __align__(16) __nv_bfloat16 g_Wgl[HDIM * KIN];    // WgnnT lo
__device__ __align__(16) __nv_bfloat16 g_hh [MROWS * HDIM];  // h hi
__device__ __align__(16) __nv_bfloat16 g_hl [MROWS * HDIM];  // h lo
__device__ __align__(16) __nv_bfloat16 g_Wch[PW * HDIM];     // Wcat^T hi
__device__ __align__(16) __nv_bfloat16 g_Wcl[PW * HDIM];     // Wcat^T lo
__device__ float g_P     [MROWS * PW];         // 16.8 MB
__device__ float g_Pw    [MROWS * 2];
__device__ float g_simnum[TEDGE];
__device__ float g_partials[BATCH];

// ==================== PTX helpers (all baseline sm_80 PTX) =================
__device__ __forceinline__ void mma_bf16(float* c, const uint32_t* a, const uint32_t* b) {
    asm volatile(
        "mma.sync.aligned.m16n8k16.row.col.f32.bf16.bf16.f32 "
        "{%0,%1,%2,%3}, {%4,%5,%6,%7}, {%8,%9}, {%0,%1,%2,%3};"
        : "+f"(c[0]), "+f"(c[1]), "+f"(c[2]), "+f"(c[3])
        : "r"(a[0]), "r"(a[1]), "r"(a[2]), "r"(a[3]), "r"(b[0]), "r"(b[1]));
}
__device__ __forceinline__ void ldsm4(uint32_t addr, uint32_t* r) {
    asm volatile("ldmatrix.sync.aligned.m8n8.x4.shared.b16 {%0,%1,%2,%3}, [%4];"
                 : "=r"(r[0]), "=r"(r[1]), "=r"(r[2]), "=r"(r[3]) : "r"(addr));
}
__device__ __forceinline__ uint32_t smem_u32(const void* p) {
    uint32_t a;
    asm("{ .reg .u64 t; cvta.to.shared.u64 t, %1; cvt.u32.u64 %0, t; }" : "=r"(a) : "l"(p));
    return a;
}
__device__ __forceinline__ void cpa16(uint32_t dst, const void* src) {
    asm volatile("cp.async.cg.shared.global [%0], [%1], 16;" :: "r"(dst), "l"(src) : "memory");
}
#define CP_COMMIT() asm volatile("cp.async.commit_group;" ::: "memory")
#define CP_WAIT1()  asm volatile("cp.async.wait_group 1;" ::: "memory")
#define CP_WAIT0()  asm volatile("cp.async.wait_group 0;" ::: "memory")

__device__ __forceinline__ void split_bf16(float v, __nv_bfloat16& h, __nv_bfloat16& l) {
    h = __float2bfloat16_rn(v);
    l = __float2bfloat16_rn(v - __bfloat162float(h));
}

// one k=64 chunk of bf16x2-compensated mma via ldmatrix, into acc[2][8][4].
// B fragments loaded per 16-col sub-tile (jj) to keep live registers low
// (R12: Bh/Bl[8][2] resident pushed 512-thr kernels to the 128-reg cap -> spills).
__device__ __forceinline__ void chunk_mma(uint32_t bAh, uint32_t bAl,
                                          uint32_t bBh, uint32_t bBl,
                                          int wm, int wn, int lane,
                                          float acc[2][8][4]) {
    const int grp = lane >> 3, rig = lane & 7;
#pragma unroll
    for (int kb = 0; kb < 4; ++kb) {
        uint32_t Ah[2][4], Al[2][4];
#pragma unroll
        for (int i = 0; i < 2; ++i) {
            uint32_t off = (uint32_t)((wm * 32 + i * 16 + (grp & 1) * 8 + rig) * RSTRB
                                      + (kb * 16 + (grp >> 1) * 8) * 2);
            ldsm4(bAh + off, Ah[i]);
            ldsm4(bAl + off, Al[i]);
        }
#pragma unroll
        for (int jj = 0; jj < 4; ++jj) {
            uint32_t Bh[2][2], Bl[2][2];
            uint32_t off = (uint32_t)((wn * 64 + jj * 16 + (grp >> 1) * 8 + rig) * RSTRB
                                      + (kb * 16 + (grp & 1) * 8) * 2);
            ldsm4(bBh + off, &Bh[0][0]);
            ldsm4(bBl + off, &Bl[0][0]);
#pragma unroll
            for (int i = 0; i < 2; ++i)
#pragma unroll
                for (int j2 = 0; j2 < 2; ++j2) {
                    float* a = acc[i][2 * jj + j2];
                    mma_bf16(a, Ah[i], Bh[j2]);   // hi*hi
                    mma_bf16(a, Ah[i], Bl[j2]);   // hi*lo
                    mma_bf16(a, Al[i], Bh[j2]);   // lo*hi
                }
        }
    }
}

// ---------------- prep: split x_cat / WgnnT / Wcat into bf16 hi/lo ---------
__global__ void k_prep(const float* __restrict__ topo, const float* __restrict__ temp,
                       const float* __restrict__ Wgnn, const float* __restrict__ Wm,
                       const float* __restrict__ Wv) {
    int idx = blockIdx.x * blockDim.x + threadIdx.x;
    if (idx < MROWS * KIN) {
        int m = idx / KIN, k = idx - m * KIN;
        float v = (k < NNODE) ? topo[m * NNODE + k] : temp[m * TDIM + (k - NNODE)];
        split_bf16(v, g_xh[idx], g_xl[idx]);
        return;
    }
    idx -= MROWS * KIN;
    if (idx < HDIM * KIN) {
        int n = idx / KIN, k = idx - n * KIN;
        split_bf16(Wgnn[k * HDIM + n], g_Wgh[idx], g_Wgl[idx]);
        return;
    }
    idx -= HDIM * KIN;
    if (idx >= PW * HDIM) return;
    int n = idx >> 8, k = idx & 255;
    float v;
    if      (n < 128) v = Wm[k * ODIM + n];
    else if (n < 256) v = Wm[(HDIM + k) * ODIM + (n - 128)];
    else if (n < 384) v = Wv[k * ODIM + (n - 256)];
    else              v = Wv[(HDIM + k) * ODIM + (n - 384)];
    split_bf16(v, g_Wch[idx], g_Wcl[idx]);
}

// stage one chunk (4 regions of 128 rows, stride KIN) via cp.async, 256 thr
__device__ __forceinline__ void issue1(uint32_t base, int tid,
                                       const __nv_bfloat16* __restrict__ Ah,
                                       const __nv_bfloat16* __restrict__ Al,
                                       const __nv_bfloat16* __restrict__ Bh,
                                       const __nv_bfloat16* __restrict__ Bl) {
#pragma unroll
    for (int q = 0; q < 4; ++q) {
        int idx = tid * 4 + q;
        int r = idx >> 3, ch = idx & 7;
        uint32_t d = base + r * RSTRB + ch * 16;
        int s = r * KIN + ch * 8;
        cpa16(d,            Ah + s);
        cpa16(d + RB_A,     Al + s);
        cpa16(d + 2 * RB_A, Bh + s);
        cpa16(d + 3 * RB_A, Bl + s);
    }
    CP_COMMIT();
}

// ====== GEMM1: h = relu(prefixmean(xcat@Wgnn)+b), stored as bf16 hi/lo =====
// grid (2, 64), 256 threads, double-buffered cp.async, K=320 in 5 chunks.
__global__ __launch_bounds__(256)
void gemm1_mma(const float* __restrict__ bias) {
    extern __shared__ uint32_t sm[];
    const uint32_t smb = smem_u32(sm);
    const int tid = threadIdx.x, lane = tid & 31, wid = tid >> 5;
    const int wm = wid >> 1, wn = wid & 1;
    const int bx = blockIdx.x, by = blockIdx.y;
    const int m0 = by * 128, n0 = bx * 128;

    const __nv_bfloat16 *Ah0 = g_xh + m0 * KIN,  *Al0 = g_xl + m0 * KIN;
    const __nv_bfloat16 *Bh0 = g_Wgh + n0 * KIN, *Bl0 = g_Wgl + n0 * KIN;

    float acc[2][8][4];
#pragma unroll
    for (int i = 0; i < 2; ++i)
#pragma unroll
        for (int j = 0; j < 8; ++j)
#pragma unroll
            for (int q = 0; q < 4; ++q) acc[i][j][q] = 0.f;

    issue1(smb,        tid, Ah0,      Al0,      Bh0,      Bl0);
    issue1(smb + BUF1, tid, Ah0 + 64, Al0 + 64, Bh0 + 64, Bl0 + 64);

#pragma unroll 1
    for (int c = 0; c < 5; ++c) {
        if (c < 4) CP_WAIT1(); else CP_WAIT0();
        __syncthreads();
        uint32_t b = smb + (c & 1) * BUF1;
        chunk_mma(b, b + RB_A, b + 2 * RB_A, b + 3 * RB_A, wm, wn, lane, acc);
        __syncthreads();
        if (c + 2 < 5) {
            int o = (c + 2) * 64;
            issue1(smb + (c & 1) * BUF1, tid, Ah0 + o, Al0 + o, Bh0 + o, Bl0 + o);
        }
    }

    // epilogue: fragments -> smem scan buffer (aliased over staging)
    __syncthreads();
    float* sD = (float*)sm;                 // 128 x 129 floats (66 KB)
    const int g = lane >> 2, t = lane & 3;
#pragma unroll
    for (int i = 0; i < 2; ++i) {
        int r0 = wm * 32 + 16 * i + g;
#pragma unroll
        for (int j = 0; j < 8; ++j) {
            int cc = wn * 64 + 8 * j + t * 2;
            sD[r0 * 129 + cc]           = acc[i][j][0];
            sD[r0 * 129 + cc + 1]       = acc[i][j][1];
            sD[(r0 + 8) * 129 + cc]     = acc[i][j][2];
            sD[(r0 + 8) * 129 + cc + 1] = acc[i][j][3];
        }
    }
    __syncthreads();

    // prefix-mean + ReLU + bf16 hi/lo split: 256 threads = 128 cols x 2 graphs
    {
        const int col = tid & 127, gph = tid >> 7;
        const float bv = bias[n0 + col];
        float s = 0.f;
        const int rb = ((by * 2 + gph) * NNODE) * HDIM + n0 + col;
#pragma unroll 4
        for (int j = 0; j < NNODE; ++j) {
            float agg = (j > 0) ? (s / (float)j) : 0.f;
            float hv = fmaxf(agg + bv, 0.f);
            __nv_bfloat16 hh, hl;
            split_bf16(hv, hh, hl);
            g_hh[rb + j * HDIM] = hh;
            g_hl[rb + j * HDIM] = hl;
            s += sD[(gph * NNODE + j) * 129 + col];
        }
    }
}

// stage one gemm2 chunk (A@128 rows, B@256 rows, stride HDIM), 512 thr
__device__ __forceinline__ void issue2(uint32_t base, int tid,
                                       const __nv_bfloat16* __restrict__ Ah,
                                       const __nv_bfloat16* __restrict__ Al,
                                       const __nv_bfloat16* __restrict__ Bh,
                                       const __nv_bfloat16* __restrict__ Bl) {
#pragma unroll
    for (int q = 0; q < 2; ++q) {
        int idx = tid * 2 + q;                  // 0..1023
        int r = idx >> 3, ch = idx & 7;
        uint32_t d = base + r * RSTRB + ch * 16;
        int s = r * HDIM + ch * 8;
        cpa16(d,        Ah + s);
        cpa16(d + RB_A, Al + s);
    }
#pragma unroll
    for (int q = 0; q < 4; ++q) {
        int idx = tid * 4 + q;                  // 0..2047
        int r = idx >> 3, ch = idx & 7;
        uint32_t d = base + 2 * RB_A + r * RSTRB + ch * 16;
        int s = r * HDIM + ch * 8;
        cpa16(d,         Bh + s);
        cpa16(d + RB_B2, Bl + s);
    }
    CP_COMMIT();
}

// ====== GEMM2: P = h @ Wcat^T.  grid (2,64), 512 threads, 128x256 tile =====
__global__ __launch_bounds__(512)
void gemm2_mma() {
    extern __shared__ uint32_t sm[];
    const uint32_t smb = smem_u32(sm);
    const int tid = threadIdx.x, lane = tid & 31, wid = tid >> 5;
    const int wm = wid & 3, wn = wid >> 2;      // 4 x 4 warp grid: 32x64 per warp
    const int bx = blockIdx.x, by = blockIdx.y;
    const int m0 = by * 128, n0 = bx * 256;

    const __nv_bfloat16 *Ah0 = g_hh + m0 * HDIM,  *Al0 = g_hl + m0 * HDIM;
    const __nv_bfloat16 *Bh0 = g_Wch + n0 * HDIM, *Bl0 = g_Wcl + n0 * HDIM;

    float acc[2][8][4];
#pragma unroll
    for (int i = 0; i < 2; ++i)
#pragma unroll
        for (int j = 0; j < 8; ++j)
#pragma unroll
            for (int q = 0; q < 4; ++q) acc[i][j][q] = 0.f;

    issue2(smb,        tid, Ah0,      Al0,      Bh0,      Bl0);
    issue2(smb + BUF2, tid, Ah0 + 64, Al0 + 64, Bh0 + 64, Bl0 + 64);

#pragma unroll 1
    for (int c = 0; c < 4; ++c) {
        if (c < 3) CP_WAIT1(); else CP_WAIT0();
        __syncthreads();
        uint32_t b = smb + (c & 1) * BUF2;
        chunk_mma(b, b + RB_A, b + 2 * RB_A, b + 2 * RB_A + RB_B2, wm, wn, lane, acc);
        __syncthreads();
        if (c + 2 < 4) {
            int o = (c + 2) * 64;
            issue2(smb + (c & 1) * BUF2, tid, Ah0 + o, Al0 + o, Bh0 + o, Bl0 + o);
        }
    }

    // epilogue: fragments -> g_P (float2 stores)
    const int g = lane >> 2, t = lane & 3;
#pragma unroll
    for (int i = 0; i < 2; ++i) {
        int r0 = m0 + wm * 32 + 16 * i + g;
#pragma unroll
        for (int j = 0; j < 8; ++j) {
            int cc = n0 + wn * 64 + 8 * j + t * 2;
            *(float2*)(g_P + r0 * PW + cc)       = make_float2(acc[i][j][0], acc[i][j][1]);
            *(float2*)(g_P + (r0 + 8) * PW + cc) = make_float2(acc[i][j][2], acc[i][j][3]);
        }
    }
}

// ---------------- skinny W_w projections (g_hh/g_hl L2-hot after gemm1) ----
__global__ __launch_bounds__(256)
void k_ww(const float* __restrict__ Ww) {
    int wid = threadIdx.x >> 5, lane = threadIdx.x & 31;
    int m = blockIdx.x * 8 + wid;               // grid = 1024
    int k = lane * 8;
    uint4 uh = *(const uint4*)(g_hh + m * HDIM + k);
    uint4 ul = *(const uint4*)(g_hl + m * HDIM + k);
    const __nv_bfloat16* hh = (const __nv_bfloat16*)&uh;
    const __nv_bfloat16* hl = (const __nv_bfloat16*)&ul;
    float s0 = 0.f, s1 = 0.f;
#pragma unroll
    for (int i = 0; i < 8; ++i) {
        float hv = __bfloat162float(hh[i]) + __bfloat162float(hl[i]);
        s0 += hv * __ldg(Ww + k + i);
        s1 += hv * __ldg(Ww + HDIM + k + i);
    }
#pragma unroll
    for (int o = 16; o; o >>= 1) {
        s0 += __shfl_down_sync(0xffffffffu, s0, o);
        s1 += __shfl_down_sync(0xffffffffu, s1, o);
    }
    if (lane == 0) { g_Pw[m * 2] = s0; g_Pw[m * 2 + 1] = s1; }
}

// ---------------- per-edge pass: sim * exp(logit), partial sums ------------
__device__ __forceinline__ float edge_term(float m, float t) {
    float sp = fmaxf(t, 0.f) + __logf(1.f + __expf(-fabsf(t)));
    return __fdividef(m * m, sp + 1.01e-6f);
}

__global__ __launch_bounds__(512)
void k_edges(const float* __restrict__ bm, const float* __restrict__ bv,
             const float* __restrict__ bw, const float* __restrict__ gum) {
    extern __shared__ float sP[];               // 64 * 532 floats, biases folded in
    __shared__ float sW[128], red[512];
    const int b = blockIdx.x, tid = threadIdx.x;

    const float* src = g_P + b * (NNODE * PW);
    for (int idx = tid; idx < NNODE * PW; idx += 512) {
        int n = idx >> 9, c = idx & 511;
        float add = 0.f;
        if (c < 128)                  add = __ldg(bm + c);
        else if (c >= 256 && c < 384) add = __ldg(bv + (c - 256));
        sP[n * PSTR + c] = src[idx] + add;
    }
    if (tid < 128) sW[tid] = g_Pw[b * 128 + tid];
    const float bww = bw[0];
    __syncthreads();

    float lsum = 0.f;
    for (int e = tid; e < EPG; e += 512) {
        // invert triangular index: base(i) = i*63 - i*(i-1)/2
        int i = (int)((127.0f - sqrtf((float)(16129 - 8 * e))) * 0.5f);
        while ((i + 1) * 63 - ((i + 1) * i) / 2 <= e) ++i;
        while (i * 63 - (i * (i - 1)) / 2 > e)        --i;
        int base = i * 63 - (i * (i - 1)) / 2;
        int j = e - base + i + 1;

        const float* ps = sP + i * PSTR;
        const float* pd = sP + j * PSTR;
        float acc = 0.f;
#pragma unroll 4
        for (int k = 0; k < ODIM; k += 4) {
            float4 a  = *(const float4*)(ps + k);
            float4 bb = *(const float4*)(pd + 128 + k);
            float4 cs = *(const float4*)(ps + 256 + k);
            float4 dd = *(const float4*)(pd + 384 + k);
            acc += edge_term(a.x + bb.x, cs.x + dd.x);
            acc += edge_term(a.y + bb.y, cs.y + dd.y);
            acc += edge_term(a.z + bb.z, cs.z + dd.z);
            acc += edge_term(a.w + bb.w, cs.w + dd.w);
        }
        float sim = __expf(acc * (-1.0f / 256.0f));
        float wl  = sW[2 * i] + sW[2 * j + 1] + bww;
        float w   = __fdividef(1.f, 1.f + __expf(-wl));
        float u   = gum[b * EPG + e];
        float gmb = -__logf(-logf(u));      // inner log FULL precision (see R11 post-mortem)
        float num = __expf((w + gmb) * 2.0f);
        g_simnum[b * EPG + e] = sim * num;
        lsum += num;
    }
    red[tid] = lsum;
    __syncthreads();
    for (int s2 = 256; s2 > 0; s2 >>= 1) {
        if (tid < s2) red[tid] += red[tid + s2];
        __syncthreads();
    }
    if (tid == 0) g_partials[b] = red[0];
}

// ---------------- fused reduce + scatter to dense adjacency ----------------
__global__ __launch_bounds__(256)
void k_final(float* __restrict__ out) {
    __shared__ float red[128];
    const int tid = threadIdx.x;
    if (tid < 128) red[tid] = g_partials[tid];
    __syncthreads();
    for (int s = 64; s > 0; s >>= 1) {
        if (tid < s) red[tid] += red[tid + s];
        __syncthreads();
    }
    const float invS = 1.0f / red[0];

    int base = (blockIdx.x * 256 + tid) * 4;
    int b = base >> 12;
    int r = (base >> 6) & 63;
    int c = base & 63;
    float v[4];
#pragma unroll
    for (int q = 0; q < 4; ++q) {
        int col = c + q;
        float x = 0.f;
        if (r < col) {
            int e = r * 63 - (r * (r - 1)) / 2 + (col - r - 1);
            x = g_simnum[b * EPG + e] * invS;
        }
        v[q] = x;
    }
    *(float4*)(out + base) = make_float4(v[0], v[1], v[2], v[3]);
}

// ---------------- launch ----------------------------------------------------
extern "C" void kernel_launch(void* const* d_in, const int* in_sizes, int n_in,
                              void* d_out, int out_size) {
    const float* topo  = (const float*)d_in[0];
    const float* temp  = (const float*)d_in[1];
    const float* gum   = (const float*)d_in[2];
    const float* Wgnn  = (const float*)d_in[3];
    const float* bgnn  = (const float*)d_in[4];
    const float* Wm    = (const float*)d_in[5];
    const float* bmn   = (const float*)d_in[6];
    const float* Wv    = (const float*)d_in[7];
    const float* bvr   = (const float*)d_in[8];
    const float* Ww    = (const float*)d_in[9];
    const float* bww   = (const float*)d_in[10];
    float* out = (float*)d_out;

    static bool init_done = false;
    if (!init_done) {
        cudaFuncSetAttribute(gemm1_mma, cudaFuncAttributeMaxDynamicSharedMemorySize, SMEM1);
        cudaFuncSetAttribute(gemm2_mma, cudaFuncAttributeMaxDynamicSharedMemorySize, SMEM2);
        cudaFuncSetAttribute(k_edges,   cudaFuncAttributeMaxDynamicSharedMemorySize, ED_SMEM);
        init_done = true;
    }

    const int prep_n = MROWS * KIN + HDIM * KIN + PW * HDIM;

    // 1. split inputs/weights into bf16 hi/lo
    k_prep<<<(prep_n + 255) / 256, 256>>>(topo, temp, Wgnn, Wm, Wv);

    // 2. h = relu(prefixmean(xcat @ Wgnn) + b) -> bf16 hi/lo (cp.async pipeline)
    gemm1_mma<<<dim3(2, MROWS / 128), 256, SMEM1>>>(bgnn);

    // 3. skinny W_w projections (h L2-resident)
    k_ww<<<MROWS / 8, 256>>>(Ww);

    // 4. P = h @ Wcat  (cp.async pipeline, 128x256 tiles, single wave)
    gemm2_mma<<<dim3(2, MROWS / 128), 512, SMEM2>>>();

    // 5. per-edge sim * exp(logit), block partial sums
    k_edges<<<BATCH, 512, ED_SMEM>>>(bmn, bvr, bww, gum);

    // 6. fused global-sum + dense adjacency scatter
    k_final<<<(BATCH * NNODE * NNODE) / (256 * 4), 256>>>(out);
}

// round 14
// speedup vs baseline: 1.2022x; 1.0579x over previous
#include <cuda_runtime.h>
#include <cuda_bf16.h>
#include <math.h>
#include <cstdint>

// Problem constants
#define BATCH   128
#define NNODE   64
#define TDIM    256
#define KIN     320          // N + T
#define HDIM    256
#define ODIM    128
#define EPG     2016         // edges per graph
#define TEDGE   (BATCH*EPG)  // 258048
#define MROWS   (BATCH*NNODE)// 8192
#define PW      512          // packed mean/var head width
#define PSTR    532          // smem row stride in edge kernel (conflict-free LDS.128)

// staged region geometry: rows of 64 bf16 (128B), row stride 144B (conflict-free LDSM)
#define RSTRB   144
#define RB_A    18432        // 128 rows * 144B
#define RB_B2   36864        // 256 rows * 144B
#define BUF1    (4 * RB_A)             // 73728  (gemm1: Ah,Al,Bh,Bl @128 rows)
#define SMEM1   (2 * BUF1 + 32)        // + 2 mbarriers
#define BUF2    (2 * RB_A + 2 * RB_B2) // 110592 (gemm2: A@128, B@256 rows)
#define SMEM2   (2 * BUF2 + 32)
#define ED_SMEM (NNODE * PSTR * 4)     // 136192
#define CH1_BYTES (4 * 128 * 128)      // 65536 per gemm1 chunk
#define CH2_BYTES (768 * 128)          // 98304 per gemm2 chunk

// ---------------- device scratch (static, allocation-free) ----------------
__device__ __align__(16) __nv_bfloat16 g_xh [MROWS * KIN];   // x_cat hi
__device__ __align__(16) __nv_bfloat16 g_xl [MROWS * KIN];   // x_cat lo
__device__ __align__(16) __nv_bfloat16 g_Wgh[HDIM * KIN];    // WgnnT hi
__device__ __align__(16) __nv_bfloat16 g_Wgl[HDIM * KIN];    // WgnnT lo
__device__ __align__(16) __nv_bfloat16 g_hh [MROWS * HDIM];  // h hi
__device__ __align__(16) __nv_bfloat16 g_hl [MROWS * HDIM];  // h lo
__device__ __align__(16) __nv_bfloat16 g_Wch[PW * HDIM];     // Wcat^T hi
__device__ __align__(16) __nv_bfloat16 g_Wcl[PW * HDIM];     // Wcat^T lo
__device__ float g_P     [MROWS * PW];         // 16.8 MB
__device__ float g_simnum[TEDGE];
__device__ float g_partials[BATCH];

// ==================== PTX helpers (sm_80/sm_90 baseline PTX) ===============
__device__ __forceinline__ void mma_bf16(float* c, const uint32_t* a, const uint32_t* b) {
    asm volatile(
        "mma.sync.aligned.m16n8k16.row.col.f32.bf16.bf16.f32 "
        "{%0,%1,%2,%3}, {%4,%5,%6,%7}, {%8,%9}, {%0,%1,%2,%3};"
        : "+f"(c[0]), "+f"(c[1]), "+f"(c[2]), "+f"(c[3])
        : "r"(a[0]), "r"(a[1]), "r"(a[2]), "r"(a[3]), "r"(b[0]), "r"(b[1]));
}
__device__ __forceinline__ void ldsm4(uint32_t addr, uint32_t* r) {
    asm volatile("ldmatrix.sync.aligned.m8n8.x4.shared.b16 {%0,%1,%2,%3}, [%4];"
                 : "=r"(r[0]), "=r"(r[1]), "=r"(r[2]), "=r"(r[3]) : "r"(addr));
}
__device__ __forceinline__ uint32_t smem_u32(const void* p) {
    uint32_t a;
    asm("{ .reg .u64 t; cvta.to.shared.u64 t, %1; cvt.u32.u64 %0, t; }" : "=r"(a) : "l"(p));
    return a;
}
// bulk async copy global -> shared (DMA path; UBLKCP in SASS), sm_90 baseline
__device__ __forceinline__ void cpbulk(uint32_t dst, const void* src, uint32_t bytes, uint32_t mbar) {
    asm volatile("cp.async.bulk.shared::cluster.global.mbarrier::complete_tx::bytes "
                 "[%0], [%1], %2, [%3];"
                 :: "r"(dst), "l"(src), "r"(bytes), "r"(mbar) : "memory");
}
#define MBAR_INIT(addr, cnt) \
    asm volatile("mbarrier.init.shared.b64 [%0], %1;" :: "r"(addr), "r"((uint32_t)(cnt)) : "memory")
#define MBAR_EXPECT_TX(addr, bytes) \
    asm volatile("mbarrier.arrive.expect_tx.shared.b64 _, [%0], %1;" :: "r"(addr), "r"((uint32_t)(bytes)) : "memory")
#define MBAR_WAIT(addr, par) do { \
    uint32_t _m = (uint32_t)(addr), _p = (uint32_t)(par), _d; \
    asm volatile("{\n\t.reg .pred p;\n\tmbarrier.try_wait.parity.acquire.cta.shared::cta.b64 p, [%1], %2;\n\tselp.b32 %0, 1, 0, p;\n\t}" \
        : "=r"(_d) : "r"(_m), "r"(_p) : "memory"); \
    if (!_d) { \
        asm volatile("{\n\t.reg .pred P1;\n\tWL_%=:\n\tmbarrier.try_wait.parity.acquire.cta.shared::cta.b64 P1, [%0], %1, 0x989680;\n\t@P1 bra.uni WD_%=;\n\tbra.uni WL_%=;\n\tWD_%=:\n\t}" \
            :: "r"(_m), "r"(_p) : "memory"); \
    } } while(0)

__device__ __forceinline__ void split_bf16(float v, __nv_bfloat16& h, __nv_bfloat16& l) {
    h = __float2bfloat16_rn(v);
    l = __float2bfloat16_rn(v - __bfloat162float(h));
}

// one k=64 chunk of bf16x2-compensated mma via ldmatrix, into acc[2][8][4]
__device__ __forceinline__ void chunk_mma(uint32_t bAh, uint32_t bAl,
                                          uint32_t bBh, uint32_t bBl,
                                          int wm, int wn, int lane,
                                          float acc[2][8][4]) {
    const int grp = lane >> 3, rig = lane & 7;
#pragma unroll
    for (int kb = 0; kb < 4; ++kb) {
        uint32_t Ah[2][4], Al[2][4];
#pragma unroll
        for (int i = 0; i < 2; ++i) {
            uint32_t off = (uint32_t)((wm * 32 + i * 16 + (grp & 1) * 8 + rig) * RSTRB
                                      + (kb * 16 + (grp >> 1) * 8) * 2);
            ldsm4(bAh + off, Ah[i]);
            ldsm4(bAl + off, Al[i]);
        }
#pragma unroll
        for (int jj = 0; jj < 4; ++jj) {
            uint32_t Bh[2][2], Bl[2][2];
            uint32_t off = (uint32_t)((wn * 64 + jj * 16 + (grp >> 1) * 8 + rig) * RSTRB
                                      + (kb * 16 + (grp & 1) * 8) * 2);
            ldsm4(bBh + off, &Bh[0][0]);
            ldsm4(bBl + off, &Bl[0][0]);
#pragma unroll
            for (int i = 0; i < 2; ++i)
#pragma unroll
                for (int j2 = 0; j2 < 2; ++j2) {
                    float* a = acc[i][2 * jj + j2];
                    mma_bf16(a, Ah[i], Bh[j2]);   // hi*hi
                    mma_bf16(a, Ah[i], Bl[j2]);   // hi*lo
                    mma_bf16(a, Al[i], Bh[j2]);   // lo*hi
                }
        }
    }
}

// ---------------- prep: split x_cat / WgnnT / Wcat into bf16 hi/lo ---------
__global__ void k_prep(const float* __restrict__ topo, const float* __restrict__ temp,
                       const float* __restrict__ Wgnn, const float* __restrict__ Wm,
                       const float* __restrict__ Wv) {
    int idx = blockIdx.x * blockDim.x + threadIdx.x;
    if (idx < MROWS * KIN) {
        int m = idx / KIN, k = idx - m * KIN;
        float v = (k < NNODE) ? topo[m * NNODE + k] : temp[m * TDIM + (k - NNODE)];
        split_bf16(v, g_xh[idx], g_xl[idx]);
        return;
    }
    idx -= MROWS * KIN;
    if (idx < HDIM * KIN) {
        int n = idx / KIN, k = idx - n * KIN;
        split_bf16(Wgnn[k * HDIM + n], g_Wgh[idx], g_Wgl[idx]);
        return;
    }
    idx -= HDIM * KIN;
    if (idx >= PW * HDIM) return;
    int n = idx >> 8, k = idx & 255;
    float v;
    if      (n < 128) v = Wm[k * ODIM + n];
    else if (n < 256) v = Wm[(HDIM + k) * ODIM + (n - 128)];
    else if (n < 384) v = Wv[k * ODIM + (n - 256)];
    else              v = Wv[(HDIM + k) * ODIM + (n - 384)];
    split_bf16(v, g_Wch[idx], g_Wcl[idx]);
}

// stage one gemm1 chunk: 512 rows of 128B via cp.async.bulk, 256 threads
__device__ __forceinline__ void issue1(uint32_t base, uint32_t mbar, int tid,
                                       const __nv_bfloat16* __restrict__ Ah,
                                       const __nv_bfloat16* __restrict__ Al,
                                       const __nv_bfloat16* __restrict__ Bh,
                                       const __nv_bfloat16* __restrict__ Bl) {
    if (tid == 0) MBAR_EXPECT_TX(mbar, CH1_BYTES);
#pragma unroll
    for (int q = 0; q < 2; ++q) {
        int r = tid + q * 256;                  // 0..511
        int reg = r >> 7, rr = r & 127;
        const __nv_bfloat16* src = (reg == 0 ? Ah : reg == 1 ? Al : reg == 2 ? Bh : Bl) + rr * KIN;
        cpbulk(base + reg * RB_A + rr * RSTRB, src, 128, mbar);
    }
}

// ====== GEMM1: h = relu(prefixmean(xcat@Wgnn)+b), stored as bf16 hi/lo =====
// grid (2, 64), 256 threads, double-buffered bulk-DMA, K=320 in 5 chunks.
__global__ __launch_bounds__(256)
void gemm1_mma(const float* __restrict__ bias) {
    extern __shared__ uint32_t sm[];
    const uint32_t smb = smem_u32(sm);
    const uint32_t mb0 = smb + 2 * BUF1, mb1 = mb0 + 16;
    const int tid = threadIdx.x, lane = tid & 31, wid = tid >> 5;
    const int wm = wid >> 1, wn = wid & 1;
    const int bx = blockIdx.x, by = blockIdx.y;
    const int m0 = by * 128, n0 = bx * 128;

    const __nv_bfloat16 *Ah0 = g_xh + m0 * KIN,  *Al0 = g_xl + m0 * KIN;
    const __nv_bfloat16 *Bh0 = g_Wgh + n0 * KIN, *Bl0 = g_Wgl + n0 * KIN;

    if (tid == 0) { MBAR_INIT(mb0, 1); MBAR_INIT(mb1, 1); }
    __syncthreads();

    float acc[2][8][4];
#pragma unroll
    for (int i = 0; i < 2; ++i)
#pragma unroll
        for (int j = 0; j < 8; ++j)
#pragma unroll
            for (int q = 0; q < 4; ++q) acc[i][j][q] = 0.f;

    issue1(smb,        mb0, tid, Ah0,      Al0,      Bh0,      Bl0);
    issue1(smb + BUF1, mb1, tid, Ah0 + 64, Al0 + 64, Bh0 + 64, Bl0 + 64);

#pragma unroll 1
    for (int c = 0; c < 5; ++c) {
        MBAR_WAIT((c & 1) ? mb1 : mb0, (c >> 1) & 1);
        uint32_t b = smb + (c & 1) * BUF1;
        chunk_mma(b, b + RB_A, b + 2 * RB_A, b + 3 * RB_A, wm, wn, lane, acc);
        __syncthreads();
        if (c + 2 < 5) {
            int o = (c + 2) * 64;
            issue1(b, (c & 1) ? mb1 : mb0, tid, Ah0 + o, Al0 + o, Bh0 + o, Bl0 + o);
        }
    }

    // epilogue: fragments -> smem scan buffer (aliased over staging)
    __syncthreads();
    float* sD = (float*)sm;                 // 128 x 129 floats (66 KB < BUF1)
    const int g = lane >> 2, t = lane & 3;
#pragma unroll
    for (int i = 0; i < 2; ++i) {
        int r0 = wm * 32 + 16 * i + g;
#pragma unroll
        for (int j = 0; j < 8; ++j) {
            int cc = wn * 64 + 8 * j + t * 2;
            sD[r0 * 129 + cc]           = acc[i][j][0];
            sD[r0 * 129 + cc + 1]       = acc[i][j][1];
            sD[(r0 + 8) * 129 + cc]     = acc[i][j][2];
            sD[(r0 + 8) * 129 + cc + 1] = acc[i][j][3];
        }
    }
    __syncthreads();

    // prefix-mean + ReLU + bf16 hi/lo split: 256 threads = 128 cols x 2 graphs
    {
        const int col = tid & 127, gph = tid >> 7;
        const float bv = bias[n0 + col];
        float s = 0.f;
        const int rb = ((by * 2 + gph) * NNODE) * HDIM + n0 + col;
#pragma unroll 4
        for (int j = 0; j < NNODE; ++j) {
            float agg = (j > 0) ? (s / (float)j) : 0.f;
            float hv = fmaxf(agg + bv, 0.f);
            __nv_bfloat16 hh, hl;
            split_bf16(hv, hh, hl);
            g_hh[rb + j * HDIM] = hh;
            g_hl[rb + j * HDIM] = hl;
            s += sD[(gph * NNODE + j) * 129 + col];
        }
    }
}

// stage one gemm2 chunk: 768 rows of 128B via cp.async.bulk, 512 threads
__device__ __forceinline__ void issue2(uint32_t base, uint32_t mbar, int tid,
                                       const __nv_bfloat16* __restrict__ Ah,
                                       const __nv_bfloat16* __restrict__ Al,
                                       const __nv_bfloat16* __restrict__ Bh,
                                       const __nv_bfloat16* __restrict__ Bl) {
    if (tid == 0) MBAR_EXPECT_TX(mbar, CH2_BYTES);
#pragma unroll 1
    for (int r = tid; r < 768; r += 512) {
        uint32_t dst; const __nv_bfloat16* src;
        if (r < 128)      { dst = base + r * RSTRB;                            src = Ah + r * HDIM; }
        else if (r < 256) { dst = base + RB_A + (r - 128) * RSTRB;             src = Al + (r - 128) * HDIM; }
        else if (r < 512) { dst = base + 2 * RB_A + (r - 256) * RSTRB;         src = Bh + (r - 256) * HDIM; }
        else              { dst = base + 2 * RB_A + RB_B2 + (r - 512) * RSTRB; src = Bl + (r - 512) * HDIM; }
        cpbulk(dst, src, 128, mbar);
    }
}

// ====== GEMM2: P = h @ Wcat^T.  grid (2,64), 512 threads, 128x256 tile =====
__global__ __launch_bounds__(512)
void gemm2_mma() {
    extern __shared__ uint32_t sm[];
    const uint32_t smb = smem_u32(sm);
    const uint32_t mb0 = smb + 2 * BUF2, mb1 = mb0 + 16;
    const int tid = threadIdx.x, lane = tid & 31, wid = tid >> 5;
    const int wm = wid & 3, wn = wid >> 2;      // 4 x 4 warp grid: 32x64 per warp
    const int bx = blockIdx.x, by = blockIdx.y;
    const int m0 = by * 128, n0 = bx * 256;

    const __nv_bfloat16 *Ah0 = g_hh + m0 * HDIM,  *Al0 = g_hl + m0 * HDIM;
    const __nv_bfloat16 *Bh0 = g_Wch + n0 * HDIM, *Bl0 = g_Wcl + n0 * HDIM;

    if (tid == 0) { MBAR_INIT(mb0, 1); MBAR_INIT(mb1, 1); }
    __syncthreads();

    float acc[2][8][4];
#pragma unroll
    for (int i = 0; i < 2; ++i)
#pragma unroll
        for (int j = 0; j < 8; ++j)
#pragma unroll
            for (int q = 0; q < 4; ++q) acc[i][j][q] = 0.f;

    issue2(smb,        mb0, tid, Ah0,      Al0,      Bh0,      Bl0);
    issue2(smb + BUF2, mb1, tid, Ah0 + 64, Al0 + 64, Bh0 + 64, Bl0 + 64);

#pragma unroll 1
    for (int c = 0; c < 4; ++c) {
        MBAR_WAIT((c & 1) ? mb1 : mb0, (c >> 1) & 1);
        uint32_t b = smb + (c & 1) * BUF2;
        chunk_mma(b, b + RB_A, b + 2 * RB_A, b + 2 * RB_A + RB_B2, wm, wn, lane, acc);
        __syncthreads();
        if (c + 2 < 4) {
            int o = (c + 2) * 64;
            issue2(b, (c & 1) ? mb1 : mb0, tid, Ah0 + o, Al0 + o, Bh0 + o, Bl0 + o);
        }
    }

    // epilogue: fragments -> g_P (float2 stores)
    const int g = lane >> 2, t = lane & 3;
#pragma unroll
    for (int i = 0; i < 2; ++i) {
        int r0 = m0 + wm * 32 + 16 * i + g;
#pragma unroll
        for (int j = 0; j < 8; ++j) {
            int cc = n0 + wn * 64 + 8 * j + t * 2;
            *(float2*)(g_P + r0 * PW + cc)       = make_float2(acc[i][j][0], acc[i][j][1]);
            *(float2*)(g_P + (r0 + 8) * PW + cc) = make_float2(acc[i][j][2], acc[i][j][3]);
        }
    }
}

// ---------------- per-edge pass (k_ww folded in): sim * exp(logit) ---------
__device__ __forceinline__ float edge_term(float m, float t) {
    float sp = fmaxf(t, 0.f) + __logf(1.f + __expf(-fabsf(t)));
    return __fdividef(m * m, sp + 1.01e-6f);
}

__global__ __launch_bounds__(512)
void k_edges(const float* __restrict__ bm, const float* __restrict__ bv,
             const float* __restrict__ bw, const float* __restrict__ gum,
             const float* __restrict__ Ww) {
    extern __shared__ float sP[];               // 64 * 532 floats, biases folded in
    __shared__ float sW[128], red[512];
    const int b = blockIdx.x, tid = threadIdx.x;
    const int wrp = tid >> 5, ln = tid & 31;

    const float* src = g_P + b * (NNODE * PW);
    for (int idx = tid; idx < NNODE * PW; idx += 512) {
        int n = idx >> 9, c = idx & 511;
        float add = 0.f;
        if (c < 128)                  add = __ldg(bm + c);
        else if (c >= 256 && c < 384) add = __ldg(bv + (c - 256));
        sP[n * PSTR + c] = src[idx] + add;
    }
    // skinny W_w projections for this graph (was k_ww): 16 warps x 4 rows
    for (int r = wrp; r < NNODE; r += 16) {
        const int m = b * NNODE + r;
        const int k = ln * 8;
        uint4 uh = *(const uint4*)(g_hh + m * HDIM + k);
        uint4 ul = *(const uint4*)(g_hl + m * HDIM + k);
        const __nv_bfloat16* hh = (const __nv_bfloat16*)&uh;
        const __nv_bfloat16* hl = (const __nv_bfloat16*)&ul;
        float s0 = 0.f, s1 = 0.f;
#pragma unroll
        for (int i = 0; i < 8; ++i) {
            float hv = __bfloat162float(hh[i]) + __bfloat162float(hl[i]);
            s0 += hv * __ldg(Ww + k + i);
            s1 += hv * __ldg(Ww + HDIM + k + i);
        }
#pragma unroll
        for (int o = 16; o; o >>= 1) {
            s0 += __shfl_down_sync(0xffffffffu, s0, o);
            s1 += __shfl_down_sync(0xffffffffu, s1, o);
        }
        if (ln == 0) { sW[2 * r] = s0; sW[2 * r + 1] = s1; }
    }
    const float bww = bw[0];
    __syncthreads();

    float lsum = 0.f;
    for (int e = tid; e < EPG; e += 512) {
        // invert triangular index: base(i) = i*63 - i*(i-1)/2
        int i = (int)((127.0f - sqrtf((float)(16129 - 8 * e))) * 0.5f);
        while ((i + 1) * 63 - ((i + 1) * i) / 2 <= e) ++i;
        while (i * 63 - (i * (i - 1)) / 2 > e)        --i;
        int base = i * 63 - (i * (i - 1)) / 2;
        int j = e - base + i + 1;

        const float* ps = sP + i * PSTR;
        const float* pd = sP + j * PSTR;
        float acc = 0.f;
#pragma unroll 4
        for (int k = 0; k < ODIM; k += 4) {
            float4 a  = *(const float4*)(ps + k);
            float4 bb = *(const float4*)(pd + 128 + k);
            float4 cs = *(const float4*)(ps + 256 + k);
            float4 dd = *(const float4*)(pd + 384 + k);
            acc += edge_term(a.x + bb.x, cs.x + dd.x);
            acc += edge_term(a.y + bb.y, cs.y + dd.y);
            acc += edge_term(a.z + bb.z, cs.z + dd.z);
            acc += edge_term(a.w + bb.w, cs.w + dd.w);
        }
        float sim = __expf(acc * (-1.0f / 256.0f));
        float wl  = sW[2 * i] + sW[2 * j + 1] + bww;
        float w   = __fdividef(1.f, 1.f + __expf(-wl));
        float u   = gum[b * EPG + e];
        float gmb = -__logf(-logf(u));      // inner log FULL precision (see R11 post-mortem)
        float num = __expf((w + gmb) * 2.0f);
        g_simnum[b * EPG + e] = sim * num;
        lsum += num;
    }
    red[tid] = lsum;
    __syncthreads();
    for (int s2 = 256; s2 > 0; s2 >>= 1) {
        if (tid < s2) red[tid] += red[tid + s2];
        __syncthreads();
    }
    if (tid == 0) g_partials[b] = red[0];
}

// ---------------- fused reduce + scatter to dense adjacency ----------------
__global__ __launch_bounds__(256)
void k_final(float* __restrict__ out) {
    __shared__ float red[128];
    const int tid = threadIdx.x;
    if (tid < 128) red[tid] = g_partials[tid];
    __syncthreads();
    for (int s = 64; s > 0; s >>= 1) {
        if (tid < s) red[tid] += red[tid + s];
        __syncthreads();
    }
    const float invS = 1.0f / red[0];

    int base = (blockIdx.x * 256 + tid) * 4;
    int b = base >> 12;
    int r = (base >> 6) & 63;
    int c = base & 63;
    float v[4];
#pragma unroll
    for (int q = 0; q < 4; ++q) {
        int col = c + q;
        float x = 0.f;
        if (r < col) {
            int e = r * 63 - (r * (r - 1)) / 2 + (col - r - 1);
            x = g_simnum[b * EPG + e] * invS;
        }
        v[q] = x;
    }
    *(float4*)(out + base) = make_float4(v[0], v[1], v[2], v[3]);
}

// ---------------- launch ----------------------------------------------------
extern "C" void kernel_launch(void* const* d_in, const int* in_sizes, int n_in,
                              void* d_out, int out_size) {
    const float* topo  = (const float*)d_in[0];
    const float* temp  = (const float*)d_in[1];
    const float* gum   = (const float*)d_in[2];
    const float* Wgnn  = (const float*)d_in[3];
    const float* bgnn  = (const float*)d_in[4];
    const float* Wm    = (const float*)d_in[5];
    const float* bmn   = (const float*)d_in[6];
    const float* Wv    = (const float*)d_in[7];
    const float* bvr   = (const float*)d_in[8];
    const float* Ww    = (const float*)d_in[9];
    const float* bww   = (const float*)d_in[10];
    float* out = (float*)d_out;

    static bool init_done = false;
    if (!init_done) {
        cudaFuncSetAttribute(gemm1_mma, cudaFuncAttributeMaxDynamicSharedMemorySize, SMEM1);
        cudaFuncSetAttribute(gemm2_mma, cudaFuncAttributeMaxDynamicSharedMemorySize, SMEM2);
        cudaFuncSetAttribute(k_edges,   cudaFuncAttributeMaxDynamicSharedMemorySize, ED_SMEM);
        init_done = true;
    }

    const int prep_n = MROWS * KIN + HDIM * KIN + PW * HDIM;

    // 1. split inputs/weights into bf16 hi/lo
    k_prep<<<(prep_n + 255) / 256, 256>>>(topo, temp, Wgnn, Wm, Wv);

    // 2. h = relu(prefixmean(xcat @ Wgnn) + b) -> bf16 hi/lo (bulk-DMA pipeline)
    gemm1_mma<<<dim3(2, MROWS / 128), 256, SMEM1>>>(bgnn);

    // 3. P = h @ Wcat  (bulk-DMA pipeline, 128x256 tiles, single wave)
    gemm2_mma<<<dim3(2, MROWS / 128), 512, SMEM2>>>();

    // 4. per-edge sim * exp(logit) + folded W_w projections
    k_edges<<<BATCH, 512, ED_SMEM>>>(bmn, bvr, bww, gum, Ww);

    // 5. fused global-sum + dense adjacency scatter
    k_final<<<(BATCH * NNODE * NNODE) / (256 * 4), 256>>>(out);
}

// round 16
// speedup vs baseline: 1.2584x; 1.0467x over previous
#include <cuda_runtime.h>
#include <cuda_bf16.h>
#include <math.h>
#include <cstdint>

// Problem constants
#define BATCH   128
#define NNODE   64
#define TDIM    256
#define KIN     320          // N + T
#define HDIM    256
#define ODIM    128
#define EPG     2016         // edges per graph
#define TEDGE   (BATCH*EPG)  // 258048
#define MROWS   (BATCH*NNODE)// 8192
#define PW      512          // packed mean/var head width
#define PSTR    532          // smem row stride in edge kernel (conflict-free LDS.128)

// staged region geometry: rows of 64 bf16 (128B), row stride 144B (conflict-free LDSM)
#define RSTRB   144
#define RB_A    18432        // 128 rows * 144B
#define RB_B2   36864        // 256 rows * 144B
#define BUF1    (4 * RB_A)             // 73728  (gemm1: Ah,Al,Bh,Bl @128 rows)
#define SMEM1   (2 * BUF1 + 32)        // + 2 mbarriers
#define BUF2    (2 * RB_A + 2 * RB_B2) // 110592 (gemm2: A@128, B@256 rows)
#define SMEM2   (2 * BUF2 + 32)
#define ED_SMEM (NNODE * PSTR * 4)     // 136192
#define CH1_BYTES (4 * 128 * 128)      // 65536 per gemm1 chunk
#define CH2_BYTES (768 * 128)          // 98304 per gemm2 chunk
#define ETHR    1024                   // k_edges threads (32 warps, occ 50%)

// ---------------- device scratch (static, allocation-free) ----------------
__device__ __align__(16) __nv_bfloat16 g_xh [MROWS * KIN];   // x_cat hi
__device__ __align__(16) __nv_bfloat16 g_xl [MROWS * KIN];   // x_cat lo
__device__ __align__(16) __nv_bfloat16 g_Wgh[HDIM * KIN];    // WgnnT hi
__device__ __align__(16) __nv_bfloat16 g_Wgl[HDIM * KIN];    // WgnnT lo
__device__ __align__(16) __nv_bfloat16 g_hh [MROWS * HDIM];  // h hi
__device__ __align__(16) __nv_bfloat16 g_hl [MROWS * HDIM];  // h lo
__device__ __align__(16) __nv_bfloat16 g_Wch[PW * HDIM];     // Wcat^T hi
__device__ __align__(16) __nv_bfloat16 g_Wcl[PW * HDIM];     // Wcat^T lo
__device__ float g_P     [MROWS * PW];         // 16.8 MB
__device__ float g_simnum[TEDGE];
__device__ float g_partials[BATCH];

// ==================== PTX helpers (sm_80/sm_90 baseline PTX) ===============
__device__ __forceinline__ void mma_bf16(float* c, const uint32_t* a, const uint32_t* b) {
    asm volatile(
        "mma.sync.aligned.m16n8k16.row.col.f32.bf16.bf16.f32 "
        "{%0,%1,%2,%3}, {%4,%5,%6,%7}, {%8,%9}, {%0,%1,%2,%3};"
        : "+f"(c[0]), "+f"(c[1]), "+f"(c[2]), "+f"(c[3])
        : "r"(a[0]), "r"(a[1]), "r"(a[2]), "r"(a[3]), "r"(b[0]), "r"(b[1]));
}
__device__ __forceinline__ void ldsm4(uint32_t addr, uint32_t* r) {
    asm volatile("ldmatrix.sync.aligned.m8n8.x4.shared.b16 {%0,%1,%2,%3}, [%4];"
                 : "=r"(r[0]), "=r"(r[1]), "=r"(r[2]), "=r"(r[3]) : "r"(addr));
}
__device__ __forceinline__ uint32_t smem_u32(const void* p) {
    uint32_t a;
    asm("{ .reg .u64 t; cvta.to.shared.u64 t, %1; cvt.u32.u64 %0, t; }" : "=r"(a) : "l"(p));
    return a;
}
// bulk async copy global -> shared (DMA path; UBLKCP in SASS), sm_90 baseline
__device__ __forceinline__ void cpbulk(uint32_t dst, const void* src, uint32_t bytes, uint32_t mbar) {
    asm volatile("cp.async.bulk.shared::cluster.global.mbarrier::complete_tx::bytes "
                 "[%0], [%1], %2, [%3];"
                 :: "r"(dst), "l"(src), "r"(bytes), "r"(mbar) : "memory");
}
#define MBAR_INIT(addr, cnt) \
    asm volatile("mbarrier.init.shared.b64 [%0], %1;" :: "r"(addr), "r"((uint32_t)(cnt)) : "memory")
#define MBAR_EXPECT_TX(addr, bytes) \
    asm volatile("mbarrier.arrive.expect_tx.shared.b64 _, [%0], %1;" :: "r"(addr), "r"((uint32_t)(bytes)) : "memory")
#define MBAR_WAIT(addr, par) do { \
    uint32_t _m = (uint32_t)(addr), _p = (uint32_t)(par), _d; \
    asm volatile("{\n\t.reg .pred p;\n\tmbarrier.try_wait.parity.acquire.cta.shared::cta.b64 p, [%1], %2;\n\tselp.b32 %0, 1, 0, p;\n\t}" \
        : "=r"(_d) : "r"(_m), "r"(_p) : "memory"); \
    if (!_d) { \
        asm volatile("{\n\t.reg .pred P1;\n\tWL_%=:\n\tmbarrier.try_wait.parity.acquire.cta.shared::cta.b64 P1, [%0], %1, 0x989680;\n\t@P1 bra.uni WD_%=;\n\tbra.uni WL_%=;\n\tWD_%=:\n\t}" \
            :: "r"(_m), "r"(_p) : "memory"); \
    } } while(0)

__device__ __forceinline__ void split_bf16(float v, __nv_bfloat16& h, __nv_bfloat16& l) {
    h = __float2bfloat16_rn(v);
    l = __float2bfloat16_rn(v - __bfloat162float(h));
}

// one k=64 chunk of bf16x2-compensated mma via ldmatrix, into acc[2][8][4]
__device__ __forceinline__ void chunk_mma(uint32_t bAh, uint32_t bAl,
                                          uint32_t bBh, uint32_t bBl,
                                          int wm, int wn, int lane,
                                          float acc[2][8][4]) {
    const int grp = lane >> 3, rig = lane & 7;
#pragma unroll
    for (int kb = 0; kb < 4; ++kb) {
        uint32_t Ah[2][4], Al[2][4];
#pragma unroll
        for (int i = 0; i < 2; ++i) {
            uint32_t off = (uint32_t)((wm * 32 + i * 16 + (grp & 1) * 8 + rig) * RSTRB
                                      + (kb * 16 + (grp >> 1) * 8) * 2);
            ldsm4(bAh + off, Ah[i]);
            ldsm4(bAl + off, Al[i]);
        }
#pragma unroll
        for (int jj = 0; jj < 4; ++jj) {
            uint32_t Bh[2][2], Bl[2][2];
            uint32_t off = (uint32_t)((wn * 64 + jj * 16 + (grp >> 1) * 8 + rig) * RSTRB
                                      + (kb * 16 + (grp & 1) * 8) * 2);
            ldsm4(bBh + off, &Bh[0][0]);
            ldsm4(bBl + off, &Bl[0][0]);
#pragma unroll
            for (int i = 0; i < 2; ++i)
#pragma unroll
                for (int j2 = 0; j2 < 2; ++j2) {
                    float* a = acc[i][2 * jj + j2];
                    mma_bf16(a, Ah[i], Bh[j2]);   // hi*hi
                    mma_bf16(a, Ah[i], Bl[j2]);   // hi*lo
                    mma_bf16(a, Al[i], Bh[j2]);   // lo*hi
                }
        }
    }
}

// ---------------- prep: split x_cat / WgnnT / Wcat into bf16 hi/lo ---------
__global__ void k_prep(const float* __restrict__ topo, const float* __restrict__ temp,
                       const float* __restrict__ Wgnn, const float* __restrict__ Wm,
                       const float* __restrict__ Wv) {
    int idx = blockIdx.x * blockDim.x + threadIdx.x;
    if (idx < MROWS * KIN) {
        int m = idx / KIN, k = idx - m * KIN;
        float v = (k < NNODE) ? topo[m * NNODE + k] : temp[m * TDIM + (k - NNODE)];
        split_bf16(v, g_xh[idx], g_xl[idx]);
        return;
    }
    idx -= MROWS * KIN;
    if (idx < HDIM * KIN) {
        int n = idx / KIN, k = idx - n * KIN;
        split_bf16(Wgnn[k * HDIM + n], g_Wgh[idx], g_Wgl[idx]);
        return;
    }
    idx -= HDIM * KIN;
    if (idx >= PW * HDIM) return;
    int n = idx >> 8, k = idx & 255;
    float v;
    if      (n < 128) v = Wm[k * ODIM + n];
    else if (n < 256) v = Wm[(HDIM + k) * ODIM + (n - 128)];
    else if (n < 384) v = Wv[k * ODIM + (n - 256)];
    else              v = Wv[(HDIM + k) * ODIM + (n - 384)];
    split_bf16(v, g_Wch[idx], g_Wcl[idx]);
}

// stage one gemm1 chunk: 512 rows of 128B via cp.async.bulk, 256 threads
__device__ __forceinline__ void issue1(uint32_t base, uint32_t mbar, int tid,
                                       const __nv_bfloat16* __restrict__ Ah,
                                       const __nv_bfloat16* __restrict__ Al,
                                       const __nv_bfloat16* __restrict__ Bh,
                                       const __nv_bfloat16* __restrict__ Bl) {
    if (tid == 0) MBAR_EXPECT_TX(mbar, CH1_BYTES);
#pragma unroll
    for (int q = 0; q < 2; ++q) {
        int r = tid + q * 256;                  // 0..511
        int reg = r >> 7, rr = r & 127;
        const __nv_bfloat16* src = (reg == 0 ? Ah : reg == 1 ? Al : reg == 2 ? Bh : Bl) + rr * KIN;
        cpbulk(base + reg * RB_A + rr * RSTRB, src, 128, mbar);
    }
}

// ====== GEMM1: h = relu(prefixmean(xcat@Wgnn)+b), stored as bf16 hi/lo =====
// grid (2, 64), 256 threads, double-buffered bulk-DMA, K=320 in 5 chunks.
__global__ __launch_bounds__(256)
void gemm1_mma(const float* __restrict__ bias) {
    extern __shared__ uint32_t sm[];
    const uint32_t smb = smem_u32(sm);
    const uint32_t mb0 = smb + 2 * BUF1, mb1 = mb0 + 16;
    const int tid = threadIdx.x, lane = tid & 31, wid = tid >> 5;
    const int wm = wid >> 1, wn = wid & 1;
    const int bx = blockIdx.x, by = blockIdx.y;
    const int m0 = by * 128, n0 = bx * 128;

    const __nv_bfloat16 *Ah0 = g_xh + m0 * KIN,  *Al0 = g_xl + m0 * KIN;
    const __nv_bfloat16 *Bh0 = g_Wgh + n0 * KIN, *Bl0 = g_Wgl + n0 * KIN;

    if (tid == 0) { MBAR_INIT(mb0, 1); MBAR_INIT(mb1, 1); }
    __syncthreads();

    float acc[2][8][4];
#pragma unroll
    for (int i = 0; i < 2; ++i)
#pragma unroll
        for (int j = 0; j < 8; ++j)
#pragma unroll
            for (int q = 0; q < 4; ++q) acc[i][j][q] = 0.f;

    issue1(smb,        mb0, tid, Ah0,      Al0,      Bh0,      Bl0);
    issue1(smb + BUF1, mb1, tid, Ah0 + 64, Al0 + 64, Bh0 + 64, Bl0 + 64);

#pragma unroll 1
    for (int c = 0; c < 5; ++c) {
        MBAR_WAIT((c & 1) ? mb1 : mb0, (c >> 1) & 1);
        uint32_t b = smb + (c & 1) * BUF1;
        chunk_mma(b, b + RB_A, b + 2 * RB_A, b + 3 * RB_A, wm, wn, lane, acc);
        __syncthreads();
        if (c + 2 < 5) {
            int o = (c + 2) * 64;
            issue1(b, (c & 1) ? mb1 : mb0, tid, Ah0 + o, Al0 + o, Bh0 + o, Bl0 + o);
        }
    }

    // epilogue: fragments -> smem scan buffer (aliased over staging)
    __syncthreads();
    float* sD = (float*)sm;                 // 128 x 129 floats (66 KB < BUF1)
    const int g = lane >> 2, t = lane & 3;
#pragma unroll
    for (int i = 0; i < 2; ++i) {
        int r0 = wm * 32 + 16 * i + g;
#pragma unroll
        for (int j = 0; j < 8; ++j) {
            int cc = wn * 64 + 8 * j + t * 2;
            sD[r0 * 129 + cc]           = acc[i][j][0];
            sD[r0 * 129 + cc + 1]       = acc[i][j][1];
            sD[(r0 + 8) * 129 + cc]     = acc[i][j][2];
            sD[(r0 + 8) * 129 + cc + 1] = acc[i][j][3];
        }
    }
    __syncthreads();

    // prefix-mean + ReLU + bf16 hi/lo split: 256 threads = 128 cols x 2 graphs
    {
        const int col = tid & 127, gph = tid >> 7;
        const float bv = bias[n0 + col];
        float s = 0.f;
        const int rb = ((by * 2 + gph) * NNODE) * HDIM + n0 + col;
#pragma unroll 4
        for (int j = 0; j < NNODE; ++j) {
            float agg = (j > 0) ? (s / (float)j) : 0.f;
            float hv = fmaxf(agg + bv, 0.f);
            __nv_bfloat16 hh, hl;
            split_bf16(hv, hh, hl);
            g_hh[rb + j * HDIM] = hh;
            g_hl[rb + j * HDIM] = hl;
            s += sD[(gph * NNODE + j) * 129 + col];
        }
    }
}

// stage one gemm2 chunk: 768 rows of 128B via cp.async.bulk, 512 threads
__device__ __forceinline__ void issue2(uint32_t base, uint32_t mbar, int tid,
                                       const __nv_bfloat16* __restrict__ Ah,
                                       const __nv_bfloat16* __restrict__ Al,
                                       const __nv_bfloat16* __restrict__ Bh,
                                       const __nv_bfloat16* __restrict__ Bl) {
    if (tid == 0) MBAR_EXPECT_TX(mbar, CH2_BYTES);
#pragma unroll 1
    for (int r = tid; r < 768; r += 512) {
        uint32_t dst; const __nv_bfloat16* src;
        if (r < 128)      { dst = base + r * RSTRB;                            src = Ah + r * HDIM; }
        else if (r < 256) { dst = base + RB_A + (r - 128) * RSTRB;             src = Al + (r - 128) * HDIM; }
        else if (r < 512) { dst = base + 2 * RB_A + (r - 256) * RSTRB;         src = Bh + (r - 256) * HDIM; }
        else              { dst = base + 2 * RB_A + RB_B2 + (r - 512) * RSTRB; src = Bl + (r - 512) * HDIM; }
        cpbulk(dst, src, 128, mbar);
    }
}

// ====== GEMM2: P = h @ Wcat^T.  grid (2,64), 512 threads, 128x256 tile =====
__global__ __launch_bounds__(512)
void gemm2_mma() {
    extern __shared__ uint32_t sm[];
    const uint32_t smb = smem_u32(sm);
    const uint32_t mb0 = smb + 2 * BUF2, mb1 = mb0 + 16;
    const int tid = threadIdx.x, lane = tid & 31, wid = tid >> 5;
    const int wm = wid & 3, wn = wid >> 2;      // 4 x 4 warp grid: 32x64 per warp
    const int bx = blockIdx.x, by = blockIdx.y;
    const int m0 = by * 128, n0 = bx * 256;

    const __nv_bfloat16 *Ah0 = g_hh + m0 * HDIM,  *Al0 = g_hl + m0 * HDIM;
    const __nv_bfloat16 *Bh0 = g_Wch + n0 * HDIM, *Bl0 = g_Wcl + n0 * HDIM;

    if (tid == 0) { MBAR_INIT(mb0, 1); MBAR_INIT(mb1, 1); }
    __syncthreads();

    float acc[2][8][4];
#pragma unroll
    for (int i = 0; i < 2; ++i)
#pragma unroll
        for (int j = 0; j < 8; ++j)
#pragma unroll
            for (int q = 0; q < 4; ++q) acc[i][j][q] = 0.f;

    issue2(smb,        mb0, tid, Ah0,      Al0,      Bh0,      Bl0);
    issue2(smb + BUF2, mb1, tid, Ah0 + 64, Al0 + 64, Bh0 + 64, Bl0 + 64);

#pragma unroll 1
    for (int c = 0; c < 4; ++c) {
        MBAR_WAIT((c & 1) ? mb1 : mb0, (c >> 1) & 1);
        uint32_t b = smb + (c & 1) * BUF2;
        chunk_mma(b, b + RB_A, b + 2 * RB_A, b + 2 * RB_A + RB_B2, wm, wn, lane, acc);
        __syncthreads();
        if (c + 2 < 4) {
            int o = (c + 2) * 64;
            issue2(b, (c & 1) ? mb1 : mb0, tid, Ah0 + o, Al0 + o, Bh0 + o, Bl0 + o);
        }
    }

    // epilogue: fragments -> g_P (float2 stores)
    const int g = lane >> 2, t = lane & 3;
#pragma unroll
    for (int i = 0; i < 2; ++i) {
        int r0 = m0 + wm * 32 + 16 * i + g;
#pragma unroll
        for (int j = 0; j < 8; ++j) {
            int cc = n0 + wn * 64 + 8 * j + t * 2;
            *(float2*)(g_P + r0 * PW + cc)       = make_float2(acc[i][j][0], acc[i][j][1]);
            *(float2*)(g_P + (r0 + 8) * PW + cc) = make_float2(acc[i][j][2], acc[i][j][3]);
        }
    }
}

// ---------------- per-edge pass (k_ww folded in): sim * exp(logit) ---------
__device__ __forceinline__ float edge_term(float m, float t) {
    float sp = fmaxf(t, 0.f) + __logf(1.f + __expf(-fabsf(t)));
    return __fdividef(m * m, sp + 1.01e-6f);
}

__global__ __launch_bounds__(ETHR)
void k_edges(const float* __restrict__ bm, const float* __restrict__ bv,
             const float* __restrict__ bw, const float* __restrict__ gum,
             const float* __restrict__ Ww) {
    extern __shared__ float sP[];               // 64 * 532 floats, biases folded in
    __shared__ float sW[128], red[ETHR];
    const int b = blockIdx.x, tid = threadIdx.x;
    const int wrp = tid >> 5, ln = tid & 31;

    const float* src = g_P + b * (NNODE * PW);
    for (int idx = tid; idx < NNODE * PW; idx += ETHR) {
        int n = idx >> 9, c = idx & 511;
        float add = 0.f;
        if (c < 128)                  add = __ldg(bm + c);
        else if (c >= 256 && c < 384) add = __ldg(bv + (c - 256));
        sP[n * PSTR + c] = src[idx] + add;
    }
    // skinny W_w projections for this graph: 32 warps x 2 rows
    for (int r = wrp; r < NNODE; r += 32) {
        const int m = b * NNODE + r;
        const int k = ln * 8;
        uint4 uh = *(const uint4*)(g_hh + m * HDIM + k);
        uint4 ul = *(const uint4*)(g_hl + m * HDIM + k);
        const __nv_bfloat16* hh = (const __nv_bfloat16*)&uh;
        const __nv_bfloat16* hl = (const __nv_bfloat16*)&ul;
        float s0 = 0.f, s1 = 0.f;
#pragma unroll
        for (int i = 0; i < 8; ++i) {
            float hv = __bfloat162float(hh[i]) + __bfloat162float(hl[i]);
            s0 += hv * __ldg(Ww + k + i);
            s1 += hv * __ldg(Ww + HDIM + k + i);
        }
#pragma unroll
        for (int o = 16; o; o >>= 1) {
            s0 += __shfl_down_sync(0xffffffffu, s0, o);
            s1 += __shfl_down_sync(0xffffffffu, s1, o);
        }
        if (ln == 0) { sW[2 * r] = s0; sW[2 * r + 1] = s1; }
    }
    const float bww = bw[0];
    __syncthreads();

    float lsum = 0.f;
    for (int e = tid; e < EPG; e += ETHR) {
        // invert triangular index: base(i) = i*63 - i*(i-1)/2
        int i = (int)((127.0f - sqrtf((float)(16129 - 8 * e))) * 0.5f);
        while ((i + 1) * 63 - ((i + 1) * i) / 2 <= e) ++i;
        while (i * 63 - (i * (i - 1)) / 2 > e)        --i;
        int base = i * 63 - (i * (i - 1)) / 2;
        int j = e - base + i + 1;

        const float* ps = sP + i * PSTR;
        const float* pd = sP + j * PSTR;
        float acc = 0.f;
#pragma unroll 4
        for (int k = 0; k < ODIM; k += 4) {
            float4 a  = *(const float4*)(ps + k);
            float4 bb = *(const float4*)(pd + 128 + k);
            float4 cs = *(const float4*)(ps + 256 + k);
            float4 dd = *(const float4*)(pd + 384 + k);
            acc += edge_term(a.x + bb.x, cs.x + dd.x);
            acc += edge_term(a.y + bb.y, cs.y + dd.y);
            acc += edge_term(a.z + bb.z, cs.z + dd.z);
            acc += edge_term(a.w + bb.w, cs.w + dd.w);
        }
        float sim = __expf(acc * (-1.0f / 256.0f));
        float wl  = sW[2 * i] + sW[2 * j + 1] + bww;
        float w   = __fdividef(1.f, 1.f + __expf(-wl));
        float u   = gum[b * EPG + e];
        float gmb = -__logf(-logf(u));      // inner log FULL precision (see R11 post-mortem)
        float num = __expf((w + gmb) * 2.0f);
        g_simnum[b * EPG + e] = sim * num;
        lsum += num;
    }
    red[tid] = lsum;
    __syncthreads();
    for (int s2 = ETHR / 2; s2 > 0; s2 >>= 1) {
        if (tid < s2) red[tid] += red[tid + s2];
        __syncthreads();
    }
    if (tid == 0) g_partials[b] = red[0];
}

// ---------------- fused reduce + scatter to dense adjacency ----------------
__global__ __launch_bounds__(256)
void k_final(float* __restrict__ out) {
    __shared__ float red[128];
    const int tid = threadIdx.x;
    if (tid < 128) red[tid] = g_partials[tid];
    __syncthreads();
    for (int s = 64; s > 0; s >>= 1) {
        if (tid < s) red[tid] += red[tid + s];
        __syncthreads();
    }
    const float invS = 1.0f / red[0];

    int base = (blockIdx.x * 256 + tid) * 4;
    int b = base >> 12;
    int r = (base >> 6) & 63;
    int c = base & 63;
    float v[4];
#pragma unroll
    for (int q = 0; q < 4; ++q) {
        int col = c + q;
        float x = 0.f;
        if (r < col) {
            int e = r * 63 - (r * (r - 1)) / 2 + (col - r - 1);
            x = g_simnum[b * EPG + e] * invS;
        }
        v[q] = x;
    }
    *(float4*)(out + base) = make_float4(v[0], v[1], v[2], v[3]);
}

// ---------------- launch ----------------------------------------------------
extern "C" void kernel_launch(void* const* d_in, const int* in_sizes, int n_in,
                              void* d_out, int out_size) {
    const float* topo  = (const float*)d_in[0];
    const float* temp  = (const float*)d_in[1];
    const float* gum   = (const float*)d_in[2];
    const float* Wgnn  = (const float*)d_in[3];
    const float* bgnn  = (const float*)d_in[4];
    const float* Wm    = (const float*)d_in[5];
    const float* bmn   = (const float*)d_in[6];
    const float* Wv    = (const float*)d_in[7];
    const float* bvr   = (const float*)d_in[8];
    const float* Ww    = (const float*)d_in[9];
    const float* bww   = (const float*)d_in[10];
    float* out = (float*)d_out;

    static bool init_done = false;
    if (!init_done) {
        cudaFuncSetAttribute(gemm1_mma, cudaFuncAttributeMaxDynamicSharedMemorySize, SMEM1);
        cudaFuncSetAttribute(gemm2_mma, cudaFuncAttributeMaxDynamicSharedMemorySize, SMEM2);
        cudaFuncSetAttribute(k_edges,   cudaFuncAttributeMaxDynamicSharedMemorySize, ED_SMEM);
        init_done = true;
    }

    const int prep_n = MROWS * KIN + HDIM * KIN + PW * HDIM;

    // 1. split inputs/weights into bf16 hi/lo
    k_prep<<<(prep_n + 255) / 256, 256>>>(topo, temp, Wgnn, Wm, Wv);

    // 2. h = relu(prefixmean(xcat @ Wgnn) + b) -> bf16 hi/lo (bulk-DMA pipeline)
    gemm1_mma<<<dim3(2, MROWS / 128), 256, SMEM1>>>(bgnn);

    // 3. P = h @ Wcat  (bulk-DMA pipeline, 128x256 tiles, single wave)
    gemm2_mma<<<dim3(2, MROWS / 128), 512, SMEM2>>>();

    // 4. per-edge sim * exp(logit) + folded W_w projections (1024 threads)
    k_edges<<<BATCH, ETHR, ED_SMEM>>>(bmn, bvr, bww, gum, Ww);

    // 5. fused global-sum + dense adjacency scatter
    k_final<<<(BATCH * NNODE * NNODE) / (256 * 4), 256>>>(out);
}